// round 7
// baseline (speedup 1.0000x reference)
#include <cuda_runtime.h>
#include <cuda_bf16.h>
#include <math.h>

#define B_ 8
#define T_ 1024
#define F_ 512
#define H_ 8
#define DK_ 64
#define P_ 2047

// -------- scratch (device globals; no allocations allowed) --------
__device__ float g_Q[(size_t)B_ * T_ * F_];                 // fp32 q proj
__device__ __nv_bfloat16 g_Kh[(size_t)B_ * T_ * F_];        // k hi
__device__ __nv_bfloat16 g_Kl[(size_t)B_ * T_ * F_];        // k lo
__device__ __nv_bfloat16 g_Vth[(size_t)B_ * H_ * DK_ * T_]; // v^T hi  [b,h,d,s]
__device__ __nv_bfloat16 g_Vtl[(size_t)B_ * H_ * DK_ * T_]; // v^T lo
__device__ __nv_bfloat16 g_Ph[(size_t)(P_ + 1) * F_];       // p hi (row 2047 spare)
__device__ __nv_bfloat16 g_Pl[(size_t)(P_ + 1) * F_];       // p lo
__device__ __nv_bfloat16 g_Ch[(size_t)B_ * T_ * F_];        // ctx hi (flash out)
__device__ __nv_bfloat16 g_Cl[(size_t)B_ * T_ * F_];        // ctx lo
// pre-converted GEMM operands (bf16 hi/lo)
__device__ __nv_bfloat16 g_Xqh[(size_t)B_ * T_ * F_], g_Xql[(size_t)B_ * T_ * F_];
__device__ __nv_bfloat16 g_Xkh[(size_t)B_ * T_ * F_], g_Xkl[(size_t)B_ * T_ * F_];
__device__ __nv_bfloat16 g_Xvh[(size_t)B_ * T_ * F_], g_Xvl[(size_t)B_ * T_ * F_];
__device__ __nv_bfloat16 g_Xph[(size_t)2048 * F_],   g_Xpl[(size_t)2048 * F_];
__device__ __nv_bfloat16 g_Wqh[(size_t)F_ * F_], g_Wql[(size_t)F_ * F_];
__device__ __nv_bfloat16 g_Wkh[(size_t)F_ * F_], g_Wkl[(size_t)F_ * F_];
__device__ __nv_bfloat16 g_Wvh[(size_t)F_ * F_], g_Wvl[(size_t)F_ * F_];
__device__ __nv_bfloat16 g_Wph[(size_t)F_ * F_], g_Wpl[(size_t)F_ * F_];
__device__ __nv_bfloat16 g_Woh[(size_t)F_ * F_], g_Wol[(size_t)F_ * F_];

// =====================================================================
// Tensor-core helpers
// =====================================================================
__device__ __forceinline__ unsigned smem_u32(const void* p) {
    return (unsigned)__cvta_generic_to_shared(p);
}

__device__ __forceinline__ void ldsm_x4(unsigned addr, unsigned& r0, unsigned& r1,
                                        unsigned& r2, unsigned& r3) {
    asm volatile("ldmatrix.sync.aligned.m8n8.x4.shared.b16 {%0,%1,%2,%3}, [%4];"
                 : "=r"(r0), "=r"(r1), "=r"(r2), "=r"(r3) : "r"(addr));
}

__device__ __forceinline__ void ldsm_x2(unsigned addr, unsigned& r0, unsigned& r1) {
    asm volatile("ldmatrix.sync.aligned.m8n8.x2.shared.b16 {%0,%1}, [%2];"
                 : "=r"(r0), "=r"(r1) : "r"(addr));
}

__device__ __forceinline__ void mma_bf16(float& c0, float& c1, float& c2, float& c3,
                                         unsigned a0, unsigned a1, unsigned a2, unsigned a3,
                                         unsigned b0, unsigned b1) {
    asm volatile(
        "mma.sync.aligned.m16n8k16.row.col.f32.bf16.bf16.f32 "
        "{%0,%1,%2,%3},{%4,%5,%6,%7},{%8,%9},{%0,%1,%2,%3};"
        : "+f"(c0), "+f"(c1), "+f"(c2), "+f"(c3)
        : "r"(a0), "r"(a1), "r"(a2), "r"(a3), "r"(b0), "r"(b1));
}

__device__ __forceinline__ void split_hl(float x, __nv_bfloat16& h, __nv_bfloat16& l) {
    h = __float2bfloat16(x);
    l = __float2bfloat16(x - __bfloat162float(h));
}

__device__ __forceinline__ void pack_hl(float x0, float x1, unsigned& hi, unsigned& lo) {
    __nv_bfloat16 h0, l0, h1, l1;
    split_hl(x0, h0, l0);
    split_hl(x1, h1, l1);
    hi = ((unsigned)__bfloat16_as_ushort(h1) << 16) | (unsigned)__bfloat16_as_ushort(h0);
    lo = ((unsigned)__bfloat16_as_ushort(l1) << 16) | (unsigned)__bfloat16_as_ushort(l0);
}

__device__ __forceinline__ void cp16(void* smem_dst, const void* gsrc) {
    unsigned d = smem_u32(smem_dst);
    asm volatile("cp.async.cg.shared.global [%0], [%1], 16;" :: "r"(d), "l"(gsrc));
}

// =====================================================================
// Prepass: fp32 -> bf16 hi/lo conversion (inputs + weights)
// =====================================================================
struct CvtJob { const float* src; __nv_bfloat16* dh; __nv_bfloat16* dl; int n4; };
struct CvtJobs { CvtJob j[9]; };

__global__ void __launch_bounds__(256) cvt_multi(CvtJobs jobs)
{
    const CvtJob jb = jobs.j[blockIdx.y];
    const int stride = gridDim.x * blockDim.x;
    for (int i = blockIdx.x * blockDim.x + threadIdx.x; i < jb.n4; i += stride) {
        float4 v = ((const float4*)jb.src)[i];
        float f[4] = {v.x, v.y, v.z, v.w};
        unsigned hs[4], ls[4];
#pragma unroll
        for (int e = 0; e < 4; e++) {
            __nv_bfloat16 h, l;
            split_hl(f[e], h, l);
            hs[e] = (unsigned)__bfloat16_as_ushort(h);
            ls[e] = (unsigned)__bfloat16_as_ushort(l);
        }
        uint2 hu = make_uint2(hs[0] | (hs[1] << 16), hs[2] | (hs[3] << 16));
        uint2 lu = make_uint2(ls[0] | (ls[1] << 16), ls[2] | (ls[3] << 16));
        *(uint2*)(jb.dh + (size_t)i * 4) = hu;
        *(uint2*)(jb.dl + (size_t)i * 4) = lu;
    }
}

// =====================================================================
// gemm_v3: bf16x3 NT GEMM on pre-split operands, cp.async double-buffered.
// C = A[M,512] @ W[512,512]^T (+bias). 128 threads, 4 warps, warp tile
// 64x64, block 128x128, BK=32.
// mode 0: fp32 -> C. mode 1: hi/lo -> (Ch,Cl). mode 2: transposed per-head.
// =====================================================================
#define G3_SMEM 81920

struct GemmJob {
    const __nv_bfloat16* Ah; const __nv_bfloat16* Al;
    const __nv_bfloat16* Wh; const __nv_bfloat16* Wl;
    const float* bias;
    float* C; __nv_bfloat16* Ch; __nv_bfloat16* Cl;
    int M; int mode;
};
struct GemmJobs { GemmJob j[4]; };

__global__ void __launch_bounds__(128) gemm_v3(GemmJobs jobs)
{
    extern __shared__ __nv_bfloat16 g3sm[];
    // layout: SAh[2][128][40], SAl, SWh, SWl  (each 10240 elems)
    __nv_bfloat16* SAh = g3sm;
    __nv_bfloat16* SAl = g3sm + 10240;
    __nv_bfloat16* SWh = g3sm + 20480;
    __nv_bfloat16* SWl = g3sm + 30720;
#define SIDX(buf, row, col) (((buf) * 128 + (row)) * 40 + (col))

    const GemmJob job = jobs.j[blockIdx.z];
    const int M = job.M;
    const int m0 = blockIdx.y * 128;
    if (m0 >= M) return;
    const int n0 = blockIdx.x * 128;

    const int tid = threadIdx.x, lane = tid & 31, warp = tid >> 5;
    const int wm = warp & 1, wn = warp >> 1;

    const int arow = lane & 15;
    const int asel = (lane >> 4) << 3;
    const int brow = ((lane >> 4) << 3) + (lane & 7);
    const int bsel = ((lane >> 3) & 1) << 3;

    const int gm = (m0 + tid < M) ? (m0 + tid) : (M - 1);
    const __nv_bfloat16* gAh = job.Ah + (size_t)gm * 512;
    const __nv_bfloat16* gAl = job.Al + (size_t)gm * 512;
    const __nv_bfloat16* gWh = job.Wh + (size_t)(n0 + tid) * 512;
    const __nv_bfloat16* gWl = job.Wl + (size_t)(n0 + tid) * 512;

    float acc[4][8][4];
#pragma unroll
    for (int i = 0; i < 4; i++)
#pragma unroll
        for (int j = 0; j < 8; j++)
#pragma unroll
            for (int q = 0; q < 4; q++) acc[i][j][q] = 0.f;

    // stage k-step s into buffer s&1 (each thread owns one row of each tile)
#define STAGE(s) do {                                                     \
        int _buf = (s) & 1, _k0 = (s) * 32;                               \
        _Pragma("unroll")                                                 \
        for (int _c = 0; _c < 4; _c++) {                                  \
            cp16(&SAh[SIDX(_buf, tid, _c * 8)], gAh + _k0 + _c * 8);      \
            cp16(&SAl[SIDX(_buf, tid, _c * 8)], gAl + _k0 + _c * 8);      \
            cp16(&SWh[SIDX(_buf, tid, _c * 8)], gWh + _k0 + _c * 8);      \
            cp16(&SWl[SIDX(_buf, tid, _c * 8)], gWl + _k0 + _c * 8);      \
        }                                                                 \
        asm volatile("cp.async.commit_group;");                           \
    } while (0)

    STAGE(0);

    for (int s = 0; s < 16; s++) {
        if (s < 15) {
            STAGE(s + 1);
            asm volatile("cp.async.wait_group 1;" ::: "memory");
        } else {
            asm volatile("cp.async.wait_group 0;" ::: "memory");
        }
        __syncthreads();
        const int buf = s & 1;

#pragma unroll
        for (int kk = 0; kk < 2; kk++) {
            const int kb = kk << 4;
            unsigned ah[4][4], al[4][4];
#pragma unroll
            for (int i = 0; i < 4; i++) {
                int r = wm * 64 + i * 16 + arow;
                ldsm_x4(smem_u32(&SAh[SIDX(buf, r, kb + asel)]),
                        ah[i][0], ah[i][1], ah[i][2], ah[i][3]);
                ldsm_x4(smem_u32(&SAl[SIDX(buf, r, kb + asel)]),
                        al[i][0], al[i][1], al[i][2], al[i][3]);
            }
#pragma unroll
            for (int jj = 0; jj < 4; jj++) {
                int nr = wn * 64 + jj * 16 + brow;
                unsigned bh0, bh1, bh2, bh3, bl0, bl1, bl2, bl3;
                ldsm_x4(smem_u32(&SWh[SIDX(buf, nr, kb + bsel)]), bh0, bh1, bh2, bh3);
                ldsm_x4(smem_u32(&SWl[SIDX(buf, nr, kb + bsel)]), bl0, bl1, bl2, bl3);
#pragma unroll
                for (int i = 0; i < 4; i++) {
                    mma_bf16(acc[i][2*jj][0], acc[i][2*jj][1], acc[i][2*jj][2], acc[i][2*jj][3],
                             ah[i][0], ah[i][1], ah[i][2], ah[i][3], bh0, bh1);
                    mma_bf16(acc[i][2*jj][0], acc[i][2*jj][1], acc[i][2*jj][2], acc[i][2*jj][3],
                             ah[i][0], ah[i][1], ah[i][2], ah[i][3], bl0, bl1);
                    mma_bf16(acc[i][2*jj][0], acc[i][2*jj][1], acc[i][2*jj][2], acc[i][2*jj][3],
                             al[i][0], al[i][1], al[i][2], al[i][3], bh0, bh1);
                    mma_bf16(acc[i][2*jj+1][0], acc[i][2*jj+1][1], acc[i][2*jj+1][2], acc[i][2*jj+1][3],
                             ah[i][0], ah[i][1], ah[i][2], ah[i][3], bh2, bh3);
                    mma_bf16(acc[i][2*jj+1][0], acc[i][2*jj+1][1], acc[i][2*jj+1][2], acc[i][2*jj+1][3],
                             ah[i][0], ah[i][1], ah[i][2], ah[i][3], bl2, bl3);
                    mma_bf16(acc[i][2*jj+1][0], acc[i][2*jj+1][1], acc[i][2*jj+1][2], acc[i][2*jj+1][3],
                             al[i][0], al[i][1], al[i][2], al[i][3], bh2, bh3);
                }
            }
        }
        __syncthreads();
    }

    // ---- epilogue ----
#pragma unroll
    for (int i = 0; i < 4; i++) {
        int mbase = m0 + wm * 64 + i * 16 + (lane >> 2);
#pragma unroll
        for (int j = 0; j < 8; j++) {
            int n = n0 + wn * 64 + j * 8 + (lane & 3) * 2;
            float bb0 = job.bias ? job.bias[n] : 0.f;
            float bb1 = job.bias ? job.bias[n + 1] : 0.f;
#pragma unroll
            for (int half = 0; half < 2; half++) {
                int m = mbase + half * 8;
                if (m >= M) continue;
                float v0 = acc[i][j][half * 2 + 0] + bb0;
                float v1 = acc[i][j][half * 2 + 1] + bb1;
                if (job.mode == 0) {
                    job.C[(size_t)m * 512 + n] = v0;
                    job.C[(size_t)m * 512 + n + 1] = v1;
                } else if (job.mode == 1) {
                    __nv_bfloat16 h0, l0, h1, l1;
                    split_hl(v0, h0, l0); split_hl(v1, h1, l1);
                    job.Ch[(size_t)m * 512 + n] = h0; job.Cl[(size_t)m * 512 + n] = l0;
                    job.Ch[(size_t)m * 512 + n + 1] = h1; job.Cl[(size_t)m * 512 + n + 1] = l1;
                } else {
                    int bb = m >> 10, ss = m & 1023;
#pragma unroll
                    for (int e = 0; e < 2; e++) {
                        int nn = n + e;
                        int hh = nn >> 6, dd = nn & 63;
                        size_t dst = (((size_t)(bb * H_ + hh) * DK_ + dd) * T_ + ss);
                        __nv_bfloat16 hv, lv;
                        split_hl(e ? v1 : v0, hv, lv);
                        job.Ch[dst] = hv; job.Cl[dst] = lv;
                    }
                }
            }
        }
    }
#undef STAGE
#undef SIDX
}

// =====================================================================
// Fused flash attention, software-pipelined with cp.async.
// 8 warps, 128 t-rows/block, grid (8, B*H). K/V double-buffered,
// P as a 256-row circular window. Epilogue writes ctx as bf16 hi/lo.
// =====================================================================
#define FL_SMEM 192768

__global__ void __launch_bounds__(256) flash_kernel(
    const float* __restrict__ pu, const float* __restrict__ pv,
    const int* __restrict__ mask)
{
    extern __shared__ char sm[];
    __nv_bfloat16* KH = (__nv_bfloat16*)(sm);             // 2 x [64][72]
    __nv_bfloat16* KL = (__nv_bfloat16*)(sm + 18432);
    __nv_bfloat16* VH = (__nv_bfloat16*)(sm + 36864);     // 2 x [64 d][72 s]
    __nv_bfloat16* VL = (__nv_bfloat16*)(sm + 55296);
    __nv_bfloat16* PH = (__nv_bfloat16*)(sm + 73728);     // [256][72] circular
    __nv_bfloat16* PL = (__nv_bfloat16*)(sm + 110592);
    float* GS  = (float*)(sm + 147456);                   // [8 warps][16][88]
    float* MSK = (float*)(sm + 192512);                   // [64]
    // prologue aliases over the P region (dead before first P prefetch)
    __nv_bfloat16* QUH = (__nv_bfloat16*)(sm + 73728);    // [128][72]
    __nv_bfloat16* QUL = (__nv_bfloat16*)(sm + 92160);
    __nv_bfloat16* QVH = (__nv_bfloat16*)(sm + 110592);
    __nv_bfloat16* QVL = (__nv_bfloat16*)(sm + 129024);

    const int tid = threadIdx.x, lane = tid & 31, warp = tid >> 5;
    const int gid = lane >> 2, tig = lane & 3;
    const int bh = blockIdx.y, b = bh >> 3, h = bh & 7;
    const int t0 = blockIdx.x * 128;
    const int pbase0 = T_ - 1 - t0 - 127;   // >= 0

    // ---- phase 0: qu/qv hi-lo staging (scaled by 1/sqrt(DK)=0.125) ----
    for (int x = tid; x < 2048; x += 256) {
        int r = x >> 4, c = (x & 15) << 2;
        float4 q4 = *(const float4*)(g_Q + ((size_t)(b * T_ + t0 + r)) * F_ + h * DK_ + c);
        float4 u4 = *(const float4*)(pu + h * DK_ + c);
        float4 v4 = *(const float4*)(pv + h * DK_ + c);
        float qs[4] = {q4.x, q4.y, q4.z, q4.w};
        float us[4] = {u4.x, u4.y, u4.z, u4.w};
        float vs[4] = {v4.x, v4.y, v4.z, v4.w};
#pragma unroll
        for (int e = 0; e < 4; e++) {
            __nv_bfloat16 hh, ll;
            split_hl((qs[e] + us[e]) * 0.125f, hh, ll);
            QUH[r * 72 + c + e] = hh; QUL[r * 72 + c + e] = ll;
            split_hl((qs[e] + vs[e]) * 0.125f, hh, ll);
            QVH[r * 72 + c + e] = hh; QVL[r * 72 + c + e] = ll;
        }
    }
    __syncthreads();

    unsigned quh[4][4], qul[4][4], qvh[4][4], qvl[4][4];
    {
        int ar = warp * 16 + (lane & 15);
        int ac = (lane >> 4) << 3;
#pragma unroll
        for (int kc = 0; kc < 4; kc++) {
            ldsm_x4(smem_u32(&QUH[ar * 72 + kc * 16 + ac]), quh[kc][0], quh[kc][1], quh[kc][2], quh[kc][3]);
            ldsm_x4(smem_u32(&QUL[ar * 72 + kc * 16 + ac]), qul[kc][0], qul[kc][1], qul[kc][2], qul[kc][3]);
            ldsm_x4(smem_u32(&QVH[ar * 72 + kc * 16 + ac]), qvh[kc][0], qvh[kc][1], qvh[kc][2], qvh[kc][3]);
            ldsm_x4(smem_u32(&QVL[ar * 72 + kc * 16 + ac]), qvl[kc][0], qvl[kc][1], qvl[kc][2], qvl[kc][3]);
        }
    }
    __syncthreads();   // P region free from here on

    // ---- initial prefetch: tile 0 K/V (buf 0) + P rows [0,192) ----
    for (int x = tid; x < 512; x += 256) {
        int r = x >> 3, c = (x & 7) << 3;
        size_t ksrc = ((size_t)(b * T_ + r)) * F_ + h * DK_ + c;
        cp16(&KH[r * 72 + c], g_Kh + ksrc);
        cp16(&KL[r * 72 + c], g_Kl + ksrc);
        size_t vsrc = ((size_t)bh * DK_ + r) * T_ + c;
        cp16(&VH[r * 72 + c], g_Vth + vsrc);
        cp16(&VL[r * 72 + c], g_Vtl + vsrc);
    }
    for (int x = tid; x < 1536; x += 256) {
        int rr = x >> 3, c = (x & 7) << 3;
        int grow = pbase0 + rr; if (grow > P_) grow = P_;
        size_t psrc = (size_t)grow * F_ + h * DK_ + c;
        cp16(&PH[rr * 72 + c], g_Ph + psrc);
        cp16(&PL[rr * 72 + c], g_Pl + psrc);
    }
    asm volatile("cp.async.commit_group;");

    float o[8][4];
#pragma unroll
    for (int nt = 0; nt < 8; nt++)
#pragma unroll
        for (int q = 0; q < 4; q++) o[nt][q] = 0.f;
    float mr0 = -1e30f, mr1 = -1e30f, l0 = 0.f, l1 = 0.f;
    float* GSw = GS + warp * (16 * 88);

    for (int i = 0; i < 16; i++) {
        const int s0 = i * 64;

        // ---- prefetch tile i+1 ----
        if (i < 15) {
            __nv_bfloat16* kh = KH + ((i + 1) & 1) * 4608;
            __nv_bfloat16* kl = KL + ((i + 1) & 1) * 4608;
            __nv_bfloat16* vh = VH + ((i + 1) & 1) * 4608;
            __nv_bfloat16* vl = VL + ((i + 1) & 1) * 4608;
            int s0n = s0 + 64;
            for (int x = tid; x < 512; x += 256) {
                int r = x >> 3, c = (x & 7) << 3;
                size_t ksrc = ((size_t)(b * T_ + s0n + r)) * F_ + h * DK_ + c;
                cp16(&kh[r * 72 + c], g_Kh + ksrc);
                cp16(&kl[r * 72 + c], g_Kl + ksrc);
                size_t vsrc = ((size_t)bh * DK_ + r) * T_ + s0n + c;
                cp16(&vh[r * 72 + c], g_Vth + vsrc);
                cp16(&vl[r * 72 + c], g_Vtl + vsrc);
            }
            int u0 = 192 + 64 * i;
            for (int x = tid; x < 512; x += 256) {
                int rr = x >> 3, c = (x & 7) << 3;
                int un = u0 + rr;
                int slot = un & 255;
                int grow = pbase0 + un; if (grow > P_) grow = P_;
                size_t psrc = (size_t)grow * F_ + h * DK_ + c;
                cp16(&PH[slot * 72 + c], g_Ph + psrc);
                cp16(&PL[slot * 72 + c], g_Pl + psrc);
            }
            asm volatile("cp.async.commit_group;");
        }
        if (tid < 64) MSK[tid] = (mask[b * T_ + s0 + tid] == 0) ? -3.0e38f : 0.f;
        if (i < 15) asm volatile("cp.async.wait_group 1;" ::: "memory");
        else        asm volatile("cp.async.wait_group 0;" ::: "memory");
        __syncthreads();

        const __nv_bfloat16* kh = KH + (i & 1) * 4608;
        const __nv_bfloat16* kl = KL + (i & 1) * 4608;
        const __nv_bfloat16* vh = VH + (i & 1) * 4608;
        const __nv_bfloat16* vl = VL + (i & 1) * 4608;
        const int off = (64 * i) & 255;

        // ---- G = qv_strip @ Pwin^T (banded BD, 80 cols per 16-strip) ----
        {
            int prow = 112 - 16 * warp + (lane & 7);
            int psel = ((lane >> 3) & 1) << 3;
#pragma unroll
            for (int nt = 0; nt < 10; nt++) {
                float g0 = 0.f, g1 = 0.f, g2 = 0.f, g3 = 0.f;
                int prw = (prow + nt * 8 + off) & 255;
#pragma unroll
                for (int kc = 0; kc < 4; kc++) {
                    unsigned p0, p1, q0, q1;
                    ldsm_x2(smem_u32(&PH[prw * 72 + kc * 16 + psel]), p0, p1);
                    ldsm_x2(smem_u32(&PL[prw * 72 + kc * 16 + psel]), q0, q1);
                    mma_bf16(g0, g1, g2, g3, qvh[kc][0], qvh[kc][1], qvh[kc][2], qvh[kc][3], p0, p1);
                    mma_bf16(g0, g1, g2, g3, qvh[kc][0], qvh[kc][1], qvh[kc][2], qvh[kc][3], q0, q1);
                    mma_bf16(g0, g1, g2, g3, qvl[kc][0], qvl[kc][1], qvl[kc][2], qvl[kc][3], p0, p1);
                }
                int gc = nt * 8 + 2 * tig;
                GSw[gid * 88 + gc] = g0;
                GSw[gid * 88 + gc + 1] = g1;
                GSw[(gid + 8) * 88 + gc] = g2;
                GSw[(gid + 8) * 88 + gc + 1] = g3;
            }
        }
        __syncwarp();

        // ---- S = qu @ K^T + band(G) + mask ----
        float sf[8][4];
        {
            int krow = lane & 7;
            int ksel = ((lane >> 3) & 1) << 3;
#pragma unroll
            for (int nt = 0; nt < 8; nt++) {
                float a0 = 0.f, a1 = 0.f, a2 = 0.f, a3 = 0.f;
#pragma unroll
                for (int kc = 0; kc < 4; kc++) {
                    unsigned k0, k1, k2, k3;
                    ldsm_x2(smem_u32(&kh[(nt * 8 + krow) * 72 + kc * 16 + ksel]), k0, k1);
                    ldsm_x2(smem_u32(&kl[(nt * 8 + krow) * 72 + kc * 16 + ksel]), k2, k3);
                    mma_bf16(a0, a1, a2, a3, quh[kc][0], quh[kc][1], quh[kc][2], quh[kc][3], k0, k1);
                    mma_bf16(a0, a1, a2, a3, quh[kc][0], quh[kc][1], quh[kc][2], quh[kc][3], k2, k3);
                    mma_bf16(a0, a1, a2, a3, qul[kc][0], qul[kc][1], qul[kc][2], qul[kc][3], k0, k1);
                }
                int col = nt * 8 + 2 * tig;
                sf[nt][0] = a0 + GSw[gid * 88 + col - gid + 15] + MSK[col];
                sf[nt][1] = a1 + GSw[gid * 88 + col - gid + 16] + MSK[col + 1];
                sf[nt][2] = a2 + GSw[(gid + 8) * 88 + col - gid + 7] + MSK[col];
                sf[nt][3] = a3 + GSw[(gid + 8) * 88 + col - gid + 8] + MSK[col + 1];
            }
        }

        // ---- online softmax ----
        float mx0 = -1e30f, mx1 = -1e30f;
#pragma unroll
        for (int nt = 0; nt < 8; nt++) {
            mx0 = fmaxf(mx0, fmaxf(sf[nt][0], sf[nt][1]));
            mx1 = fmaxf(mx1, fmaxf(sf[nt][2], sf[nt][3]));
        }
        mx0 = fmaxf(mx0, __shfl_xor_sync(0xffffffffu, mx0, 1));
        mx0 = fmaxf(mx0, __shfl_xor_sync(0xffffffffu, mx0, 2));
        mx1 = fmaxf(mx1, __shfl_xor_sync(0xffffffffu, mx1, 1));
        mx1 = fmaxf(mx1, __shfl_xor_sync(0xffffffffu, mx1, 2));
        float mn0 = fmaxf(mr0, mx0), mn1 = fmaxf(mr1, mx1);
        float sc0 = __expf(mr0 - mn0), sc1 = __expf(mr1 - mn1);
        float su0 = 0.f, su1 = 0.f;
#pragma unroll
        for (int nt = 0; nt < 8; nt++) {
            sf[nt][0] = __expf(sf[nt][0] - mn0);
            sf[nt][1] = __expf(sf[nt][1] - mn0);
            sf[nt][2] = __expf(sf[nt][2] - mn1);
            sf[nt][3] = __expf(sf[nt][3] - mn1);
            su0 += sf[nt][0] + sf[nt][1];
            su1 += sf[nt][2] + sf[nt][3];
        }
        su0 += __shfl_xor_sync(0xffffffffu, su0, 1);
        su0 += __shfl_xor_sync(0xffffffffu, su0, 2);
        su1 += __shfl_xor_sync(0xffffffffu, su1, 1);
        su1 += __shfl_xor_sync(0xffffffffu, su1, 2);
        l0 = l0 * sc0 + su0;
        l1 = l1 * sc1 + su1;
        mr0 = mn0; mr1 = mn1;
#pragma unroll
        for (int nt = 0; nt < 8; nt++) {
            o[nt][0] *= sc0; o[nt][1] *= sc0;
            o[nt][2] *= sc1; o[nt][3] *= sc1;
        }

        // ---- O += P @ V ----
        {
            int vrow = lane & 7;
            int vsel = ((lane >> 3) & 1) << 3;
#pragma unroll
            for (int kc = 0; kc < 4; kc++) {
                unsigned ah[4], al[4];
                pack_hl(sf[2 * kc][0], sf[2 * kc][1], ah[0], al[0]);
                pack_hl(sf[2 * kc][2], sf[2 * kc][3], ah[1], al[1]);
                pack_hl(sf[2 * kc + 1][0], sf[2 * kc + 1][1], ah[2], al[2]);
                pack_hl(sf[2 * kc + 1][2], sf[2 * kc + 1][3], ah[3], al[3]);
#pragma unroll
                for (int nt = 0; nt < 8; nt++) {
                    unsigned v0, v1, w0, w1;
                    ldsm_x2(smem_u32(&vh[(nt * 8 + vrow) * 72 + kc * 16 + vsel]), v0, v1);
                    ldsm_x2(smem_u32(&vl[(nt * 8 + vrow) * 72 + kc * 16 + vsel]), w0, w1);
                    mma_bf16(o[nt][0], o[nt][1], o[nt][2], o[nt][3],
                             ah[0], ah[1], ah[2], ah[3], v0, v1);
                    mma_bf16(o[nt][0], o[nt][1], o[nt][2], o[nt][3],
                             ah[0], ah[1], ah[2], ah[3], w0, w1);
                    mma_bf16(o[nt][0], o[nt][1], o[nt][2], o[nt][3],
                             al[0], al[1], al[2], al[3], v0, v1);
                }
            }
        }
        __syncthreads();
    }

    // ---- epilogue: write ctx as bf16 hi/lo ----
    float inv0 = (l0 > 0.f) ? 1.f / l0 : 0.f;
    float inv1 = (l1 > 0.f) ? 1.f / l1 : 0.f;
    int row0 = t0 + warp * 16 + gid;
#pragma unroll
    for (int nt = 0; nt < 8; nt++) {
        int colg = h * DK_ + nt * 8 + 2 * tig;
        unsigned hi0, lo0, hi1, lo1;
        pack_hl(o[nt][0] * inv0, o[nt][1] * inv0, hi0, lo0);
        pack_hl(o[nt][2] * inv1, o[nt][3] * inv1, hi1, lo1);
        size_t d0 = ((size_t)(b * T_ + row0)) * F_ + colg;
        size_t d1 = ((size_t)(b * T_ + row0 + 8)) * F_ + colg;
        *(unsigned*)&g_Ch[d0] = hi0; *(unsigned*)&g_Cl[d0] = lo0;
        *(unsigned*)&g_Ch[d1] = hi1; *(unsigned*)&g_Cl[d1] = lo1;
    }
}

// =====================================================================
extern "C" void kernel_launch(void* const* d_in, const int* in_sizes, int n_in,
                              void* d_out, int out_size)
{
    const float* query   = (const float*)d_in[0];
    const float* key_in  = (const float*)d_in[1];
    const float* value   = (const float*)d_in[2];
    const float* pos_emb = (const float*)d_in[3];
    const int*   mask    = (const int*)d_in[4];
    const float* Wq = (const float*)d_in[5];
    const float* bq = (const float*)d_in[6];
    const float* Wk = (const float*)d_in[7];
    const float* bk = (const float*)d_in[8];
    const float* Wv = (const float*)d_in[9];
    const float* bv = (const float*)d_in[10];
    const float* Wo = (const float*)d_in[11];
    const float* bo = (const float*)d_in[12];
    const float* Wp = (const float*)d_in[13];
    const float* pu = (const float*)d_in[14];
    const float* pv = (const float*)d_in[15];
    float* out = (float*)d_out;

    float* Qp;
    __nv_bfloat16 *Khp, *Klp, *Vthp, *Vtlp, *Php, *Plp, *Chp, *Clp;
    __nv_bfloat16 *Xqh, *Xql, *Xkh, *Xkl, *Xvh, *Xvl, *Xph, *Xpl;
    __nv_bfloat16 *Wqh, *Wql, *Wkh, *Wkl, *Wvh, *Wvl, *Wph, *Wpl, *Woh, *Wol;
    cudaGetSymbolAddress((void**)&Qp,   g_Q);
    cudaGetSymbolAddress((void**)&Khp,  g_Kh);  cudaGetSymbolAddress((void**)&Klp,  g_Kl);
    cudaGetSymbolAddress((void**)&Vthp, g_Vth); cudaGetSymbolAddress((void**)&Vtlp, g_Vtl);
    cudaGetSymbolAddress((void**)&Php,  g_Ph);  cudaGetSymbolAddress((void**)&Plp,  g_Pl);
    cudaGetSymbolAddress((void**)&Chp,  g_Ch);  cudaGetSymbolAddress((void**)&Clp,  g_Cl);
    cudaGetSymbolAddress((void**)&Xqh,  g_Xqh); cudaGetSymbolAddress((void**)&Xql,  g_Xql);
    cudaGetSymbolAddress((void**)&Xkh,  g_Xkh); cudaGetSymbolAddress((void**)&Xkl,  g_Xkl);
    cudaGetSymbolAddress((void**)&Xvh,  g_Xvh); cudaGetSymbolAddress((void**)&Xvl,  g_Xvl);
    cudaGetSymbolAddress((void**)&Xph,  g_Xph); cudaGetSymbolAddress((void**)&Xpl,  g_Xpl);
    cudaGetSymbolAddress((void**)&Wqh,  g_Wqh); cudaGetSymbolAddress((void**)&Wql,  g_Wql);
    cudaGetSymbolAddress((void**)&Wkh,  g_Wkh); cudaGetSymbolAddress((void**)&Wkl,  g_Wkl);
    cudaGetSymbolAddress((void**)&Wvh,  g_Wvh); cudaGetSymbolAddress((void**)&Wvl,  g_Wvl);
    cudaGetSymbolAddress((void**)&Wph,  g_Wph); cudaGetSymbolAddress((void**)&Wpl,  g_Wpl);
    cudaGetSymbolAddress((void**)&Woh,  g_Woh); cudaGetSymbolAddress((void**)&Wol,  g_Wol);

    cudaFuncSetAttribute(flash_kernel, cudaFuncAttributeMaxDynamicSharedMemorySize, FL_SMEM);
    cudaFuncSetAttribute(gemm_v3, cudaFuncAttributeMaxDynamicSharedMemorySize, G3_SMEM);

    // ---- prepass: fp32 -> bf16 hi/lo for all GEMM operands ----
    const int NBT = B_ * T_ * F_ / 4;          // 1048576
    const int NP  = P_ * F_ / 4;               // 262016
    const int NW  = F_ * F_ / 4;               // 65536
    CvtJobs cj;
    cj.j[0] = { query,   Xqh, Xql, NBT };
    cj.j[1] = { key_in,  Xkh, Xkl, NBT };
    cj.j[2] = { value,   Xvh, Xvl, NBT };
    cj.j[3] = { pos_emb, Xph, Xpl, NP  };
    cj.j[4] = { Wq, Wqh, Wql, NW };
    cj.j[5] = { Wk, Wkh, Wkl, NW };
    cj.j[6] = { Wv, Wvh, Wvl, NW };
    cj.j[7] = { Wp, Wph, Wpl, NW };
    cj.j[8] = { Wo, Woh, Wol, NW };
    cvt_multi<<<dim3(512, 9), 256>>>(cj);

    // ---- all 4 input projections in ONE launch (grid.z = job id) ----
    GemmJobs pj;
    pj.j[0] = { Xqh, Xql, Wqh, Wql, bq,      Qp,      nullptr, nullptr, B_ * T_, 0 };
    pj.j[1] = { Xkh, Xkl, Wkh, Wkl, bk,      nullptr, Khp,     Klp,     B_ * T_, 1 };
    pj.j[2] = { Xvh, Xvl, Wvh, Wvl, bv,      nullptr, Vthp,    Vtlp,    B_ * T_, 2 };
    pj.j[3] = { Xph, Xpl, Wph, Wpl, nullptr, nullptr, Php,     Plp,     P_,      1 };
    gemm_v3<<<dim3(4, 64, 4), 128, G3_SMEM>>>(pj);

    // fused attention (scores + rel-shift + softmax + AV), pipelined
    flash_kernel<<<dim3(8, B_ * H_), 256, FL_SMEM>>>(pu, pv, mask);

    // output projection (A = ctx hi/lo written by flash)
    GemmJobs oj;
    oj.j[0] = { Chp, Clp, Woh, Wol, bo, out, nullptr, nullptr, B_ * T_, 0 };
    oj.j[1] = oj.j[0]; oj.j[2] = oj.j[0]; oj.j[3] = oj.j[0];
    gemm_v3<<<dim3(4, 64, 1), 128, G3_SMEM>>>(oj);
}

// round 8
// speedup vs baseline: 1.1584x; 1.1584x over previous
#include <cuda_runtime.h>
#include <cuda_bf16.h>
#include <math.h>

#define B_ 8
#define T_ 1024
#define F_ 512
#define H_ 8
#define DK_ 64
#define P_ 2047

// -------- scratch (device globals; no allocations allowed) --------
__device__ float g_Q[(size_t)B_ * T_ * F_];                 // fp32 q proj
__device__ __nv_bfloat16 g_Kh[(size_t)B_ * T_ * F_];        // k hi
__device__ __nv_bfloat16 g_Kl[(size_t)B_ * T_ * F_];        // k lo
__device__ __nv_bfloat16 g_Vth[(size_t)B_ * H_ * DK_ * T_]; // v^T hi  [b,h,d,s]
__device__ __nv_bfloat16 g_Vtl[(size_t)B_ * H_ * DK_ * T_]; // v^T lo
__device__ __nv_bfloat16 g_Ph[(size_t)(P_ + 1) * F_];       // p hi (row 2047 spare)
__device__ __nv_bfloat16 g_Pl[(size_t)(P_ + 1) * F_];       // p lo
__device__ float g_ctx[(size_t)B_ * T_ * F_];

// =====================================================================
// Tensor-core helpers
// =====================================================================
__device__ __forceinline__ unsigned smem_u32(const void* p) {
    return (unsigned)__cvta_generic_to_shared(p);
}

__device__ __forceinline__ void ldsm_x4(unsigned addr, unsigned& r0, unsigned& r1,
                                        unsigned& r2, unsigned& r3) {
    asm volatile("ldmatrix.sync.aligned.m8n8.x4.shared.b16 {%0,%1,%2,%3}, [%4];"
                 : "=r"(r0), "=r"(r1), "=r"(r2), "=r"(r3) : "r"(addr));
}

__device__ __forceinline__ void ldsm_x2(unsigned addr, unsigned& r0, unsigned& r1) {
    asm volatile("ldmatrix.sync.aligned.m8n8.x2.shared.b16 {%0,%1}, [%2];"
                 : "=r"(r0), "=r"(r1) : "r"(addr));
}

__device__ __forceinline__ void mma_bf16(float& c0, float& c1, float& c2, float& c3,
                                         unsigned a0, unsigned a1, unsigned a2, unsigned a3,
                                         unsigned b0, unsigned b1) {
    asm volatile(
        "mma.sync.aligned.m16n8k16.row.col.f32.bf16.bf16.f32 "
        "{%0,%1,%2,%3},{%4,%5,%6,%7},{%8,%9},{%0,%1,%2,%3};"
        : "+f"(c0), "+f"(c1), "+f"(c2), "+f"(c3)
        : "r"(a0), "r"(a1), "r"(a2), "r"(a3), "r"(b0), "r"(b1));
}

__device__ __forceinline__ void split_hl(float x, __nv_bfloat16& h, __nv_bfloat16& l) {
    h = __float2bfloat16(x);
    l = __float2bfloat16(x - __bfloat162float(h));
}

__device__ __forceinline__ void pack_hl(float x0, float x1, unsigned& hi, unsigned& lo) {
    __nv_bfloat16 h0, l0, h1, l1;
    split_hl(x0, h0, l0);
    split_hl(x1, h1, l1);
    hi = ((unsigned)__bfloat16_as_ushort(h1) << 16) | (unsigned)__bfloat16_as_ushort(h0);
    lo = ((unsigned)__bfloat16_as_ushort(l1) << 16) | (unsigned)__bfloat16_as_ushort(l0);
}

__device__ __forceinline__ void cvt4(__nv_bfloat16* dh, __nv_bfloat16* dl, float4 v) {
    float f[4] = {v.x, v.y, v.z, v.w};
#pragma unroll
    for (int i = 0; i < 4; i++) split_hl(f[i], dh[i], dl[i]);
}

__device__ __forceinline__ void cp16(void* smem_dst, const void* gsrc) {
    unsigned d = smem_u32(smem_dst);
    asm volatile("cp.async.cg.shared.global [%0], [%1], 16;" :: "r"(d), "l"(gsrc));
}

// =====================================================================
// bf16x3 tensor-core NT GEMM, multi-job batched over grid.z.
// (exact R6 version — known good at 182us/46us)
// =====================================================================
#define BK_ 32
#define LDSA (BK_ + 8)
#define GN_ 512
#define GK_ 512

struct GemmJob {
    const float* A; const float* W; const float* bias;
    float* C; __nv_bfloat16* Ch; __nv_bfloat16* Cl;
    int M; int mode;
};
struct GemmJobs { GemmJob j[4]; };

__global__ void __launch_bounds__(256) gemm_multi(GemmJobs jobs)
{
    __shared__ __nv_bfloat16 Ah[128][LDSA], Al[128][LDSA];
    __shared__ __nv_bfloat16 Wh[128][LDSA], Wl[128][LDSA];

    const GemmJob job = jobs.j[blockIdx.z];
    const int M = job.M;
    const int m0 = blockIdx.y * 128;
    if (m0 >= M) return;
    const int n0 = blockIdx.x * 128;

    const float* __restrict__ A = job.A;
    const float* __restrict__ W = job.W;

    const int tid = threadIdx.x;
    const int lane = tid & 31;
    const int warp = tid >> 5;
    const int wm = warp & 1;
    const int wn = warp >> 1;

    const int arow = lane & 15;
    const int asel = (lane >> 4) << 3;
    const int bn_off = lane & 7;
    const int bsel = ((lane >> 3) & 1) << 3;

    float acc[4][4][4];
#pragma unroll
    for (int i = 0; i < 4; i++)
#pragma unroll
        for (int j = 0; j < 4; j++)
#pragma unroll
            for (int q = 0; q < 4; q++) acc[i][j][q] = 0.f;

    for (int k0 = 0; k0 < GK_; k0 += BK_) {
#pragma unroll
        for (int q = 0; q < 4; q++) {
            int idx = tid + q * 256;
            int row = idx >> 3;
            int col = (idx & 7) << 2;
            int gm = m0 + row; if (gm >= M) gm = M - 1;
            float4 a4 = *(const float4*)(A + (size_t)gm * GK_ + k0 + col);
            cvt4(&Ah[row][col], &Al[row][col], a4);
            int gn = n0 + row;
            float4 w4 = *(const float4*)(W + (size_t)gn * GK_ + k0 + col);
            cvt4(&Wh[row][col], &Wl[row][col], w4);
        }
        __syncthreads();

#pragma unroll
        for (int kk = 0; kk < 2; kk++) {
            const int kb = kk << 4;
            unsigned ah[4][4], al[4][4], bh[4][2], bl[4][2];
#pragma unroll
            for (int i = 0; i < 4; i++) {
                int r = wm * 64 + i * 16 + arow;
                ldsm_x4(smem_u32(&Ah[r][kb + asel]), ah[i][0], ah[i][1], ah[i][2], ah[i][3]);
                ldsm_x4(smem_u32(&Al[r][kb + asel]), al[i][0], al[i][1], al[i][2], al[i][3]);
            }
#pragma unroll
            for (int j = 0; j < 4; j++) {
                int n = wn * 32 + j * 8 + bn_off;
                ldsm_x2(smem_u32(&Wh[n][kb + bsel]), bh[j][0], bh[j][1]);
                ldsm_x2(smem_u32(&Wl[n][kb + bsel]), bl[j][0], bl[j][1]);
            }
#pragma unroll
            for (int i = 0; i < 4; i++)
#pragma unroll
                for (int j = 0; j < 4; j++) {
                    mma_bf16(acc[i][j][0], acc[i][j][1], acc[i][j][2], acc[i][j][3],
                             ah[i][0], ah[i][1], ah[i][2], ah[i][3], bh[j][0], bh[j][1]);
                    mma_bf16(acc[i][j][0], acc[i][j][1], acc[i][j][2], acc[i][j][3],
                             ah[i][0], ah[i][1], ah[i][2], ah[i][3], bl[j][0], bl[j][1]);
                    mma_bf16(acc[i][j][0], acc[i][j][1], acc[i][j][2], acc[i][j][3],
                             al[i][0], al[i][1], al[i][2], al[i][3], bh[j][0], bh[j][1]);
                }
        }
        __syncthreads();
    }

#pragma unroll
    for (int i = 0; i < 4; i++) {
        int mbase = m0 + wm * 64 + i * 16 + (lane >> 2);
#pragma unroll
        for (int j = 0; j < 4; j++) {
            int n = n0 + wn * 32 + j * 8 + (lane & 3) * 2;
            float bb0 = job.bias ? job.bias[n] : 0.f;
            float bb1 = job.bias ? job.bias[n + 1] : 0.f;
#pragma unroll
            for (int half = 0; half < 2; half++) {
                int m = mbase + half * 8;
                if (m >= M) continue;
                float v0 = acc[i][j][half * 2 + 0] + bb0;
                float v1 = acc[i][j][half * 2 + 1] + bb1;
                if (job.mode == 0) {
                    job.C[(size_t)m * GN_ + n] = v0;
                    job.C[(size_t)m * GN_ + n + 1] = v1;
                } else if (job.mode == 1) {
                    __nv_bfloat16 h0, l0, h1, l1;
                    split_hl(v0, h0, l0); split_hl(v1, h1, l1);
                    job.Ch[(size_t)m * GN_ + n] = h0; job.Cl[(size_t)m * GN_ + n] = l0;
                    job.Ch[(size_t)m * GN_ + n + 1] = h1; job.Cl[(size_t)m * GN_ + n + 1] = l1;
                } else {
                    int bb = m >> 10, ss = m & 1023;
#pragma unroll
                    for (int e = 0; e < 2; e++) {
                        int nn = n + e;
                        int hh = nn >> 6, dd = nn & 63;
                        size_t dst = (((size_t)(bb * H_ + hh) * DK_ + dd) * T_ + ss);
                        __nv_bfloat16 hv, lv;
                        split_hl(e ? v1 : v0, hv, lv);
                        job.Ch[dst] = hv; job.Cl[dst] = lv;
                    }
                }
            }
        }
    }
}

// =====================================================================
// Fused flash attention, software-pipelined with cp.async.
// R6 structure; this round: split MMA accumulation chains (2 independent
// accumulator sets per phase) to break accumulator RAW serialization.
// =====================================================================
#define FL_SMEM 192768

__global__ void __launch_bounds__(256) flash_kernel(
    const float* __restrict__ pu, const float* __restrict__ pv,
    const int* __restrict__ mask)
{
    extern __shared__ char sm[];
    __nv_bfloat16* KH = (__nv_bfloat16*)(sm);             // 2 x [64][72]
    __nv_bfloat16* KL = (__nv_bfloat16*)(sm + 18432);
    __nv_bfloat16* VH = (__nv_bfloat16*)(sm + 36864);     // 2 x [64 d][72 s]
    __nv_bfloat16* VL = (__nv_bfloat16*)(sm + 55296);
    __nv_bfloat16* PH = (__nv_bfloat16*)(sm + 73728);     // [256][72] circular
    __nv_bfloat16* PL = (__nv_bfloat16*)(sm + 110592);
    float* GS  = (float*)(sm + 147456);                   // [8 warps][16][88]
    float* MSK = (float*)(sm + 192512);                   // [64]
    // prologue aliases over the P region (dead before first P prefetch)
    __nv_bfloat16* QUH = (__nv_bfloat16*)(sm + 73728);    // [128][72]
    __nv_bfloat16* QUL = (__nv_bfloat16*)(sm + 92160);
    __nv_bfloat16* QVH = (__nv_bfloat16*)(sm + 110592);
    __nv_bfloat16* QVL = (__nv_bfloat16*)(sm + 129024);

    const int tid = threadIdx.x, lane = tid & 31, warp = tid >> 5;
    const int gid = lane >> 2, tig = lane & 3;
    const int bh = blockIdx.y, b = bh >> 3, h = bh & 7;
    const int t0 = blockIdx.x * 128;
    const int pbase0 = T_ - 1 - t0 - 127;   // >= 0

    // ---- phase 0: qu/qv hi-lo staging (scaled by 1/sqrt(DK)=0.125) ----
    for (int x = tid; x < 2048; x += 256) {
        int r = x >> 4, c = (x & 15) << 2;
        float4 q4 = *(const float4*)(g_Q + ((size_t)(b * T_ + t0 + r)) * F_ + h * DK_ + c);
        float4 u4 = *(const float4*)(pu + h * DK_ + c);
        float4 v4 = *(const float4*)(pv + h * DK_ + c);
        float qs[4] = {q4.x, q4.y, q4.z, q4.w};
        float us[4] = {u4.x, u4.y, u4.z, u4.w};
        float vs[4] = {v4.x, v4.y, v4.z, v4.w};
#pragma unroll
        for (int e = 0; e < 4; e++) {
            __nv_bfloat16 hh, ll;
            split_hl((qs[e] + us[e]) * 0.125f, hh, ll);
            QUH[r * 72 + c + e] = hh; QUL[r * 72 + c + e] = ll;
            split_hl((qs[e] + vs[e]) * 0.125f, hh, ll);
            QVH[r * 72 + c + e] = hh; QVL[r * 72 + c + e] = ll;
        }
    }
    __syncthreads();

    unsigned quh[4][4], qul[4][4], qvh[4][4], qvl[4][4];
    {
        int ar = warp * 16 + (lane & 15);
        int ac = (lane >> 4) << 3;
#pragma unroll
        for (int kc = 0; kc < 4; kc++) {
            ldsm_x4(smem_u32(&QUH[ar * 72 + kc * 16 + ac]), quh[kc][0], quh[kc][1], quh[kc][2], quh[kc][3]);
            ldsm_x4(smem_u32(&QUL[ar * 72 + kc * 16 + ac]), qul[kc][0], qul[kc][1], qul[kc][2], qul[kc][3]);
            ldsm_x4(smem_u32(&QVH[ar * 72 + kc * 16 + ac]), qvh[kc][0], qvh[kc][1], qvh[kc][2], qvh[kc][3]);
            ldsm_x4(smem_u32(&QVL[ar * 72 + kc * 16 + ac]), qvl[kc][0], qvl[kc][1], qvl[kc][2], qvl[kc][3]);
        }
    }
    __syncthreads();   // P region free from here on

    // ---- initial prefetch: tile 0 K/V (buf 0) + P rows [0,192) ----
    for (int x = tid; x < 512; x += 256) {
        int r = x >> 3, c = (x & 7) << 3;
        size_t ksrc = ((size_t)(b * T_ + r)) * F_ + h * DK_ + c;
        cp16(&KH[r * 72 + c], g_Kh + ksrc);
        cp16(&KL[r * 72 + c], g_Kl + ksrc);
        size_t vsrc = ((size_t)bh * DK_ + r) * T_ + c;
        cp16(&VH[r * 72 + c], g_Vth + vsrc);
        cp16(&VL[r * 72 + c], g_Vtl + vsrc);
    }
    for (int x = tid; x < 1536; x += 256) {
        int rr = x >> 3, c = (x & 7) << 3;
        int grow = pbase0 + rr; if (grow > P_) grow = P_;
        size_t psrc = (size_t)grow * F_ + h * DK_ + c;
        cp16(&PH[rr * 72 + c], g_Ph + psrc);
        cp16(&PL[rr * 72 + c], g_Pl + psrc);
    }
    asm volatile("cp.async.commit_group;");

    float o[8][4], oL[8][4];
#pragma unroll
    for (int nt = 0; nt < 8; nt++)
#pragma unroll
        for (int q = 0; q < 4; q++) { o[nt][q] = 0.f; oL[nt][q] = 0.f; }
    float mr0 = -1e30f, mr1 = -1e30f, l0 = 0.f, l1 = 0.f;
    float* GSw = GS + warp * (16 * 88);

    for (int i = 0; i < 16; i++) {
        const int s0 = i * 64;

        // ---- prefetch tile i+1 ----
        if (i < 15) {
            __nv_bfloat16* kh = KH + ((i + 1) & 1) * 4608;
            __nv_bfloat16* kl = KL + ((i + 1) & 1) * 4608;
            __nv_bfloat16* vh = VH + ((i + 1) & 1) * 4608;
            __nv_bfloat16* vl = VL + ((i + 1) & 1) * 4608;
            int s0n = s0 + 64;
            for (int x = tid; x < 512; x += 256) {
                int r = x >> 3, c = (x & 7) << 3;
                size_t ksrc = ((size_t)(b * T_ + s0n + r)) * F_ + h * DK_ + c;
                cp16(&kh[r * 72 + c], g_Kh + ksrc);
                cp16(&kl[r * 72 + c], g_Kl + ksrc);
                size_t vsrc = ((size_t)bh * DK_ + r) * T_ + s0n + c;
                cp16(&vh[r * 72 + c], g_Vth + vsrc);
                cp16(&vl[r * 72 + c], g_Vtl + vsrc);
            }
            int u0 = 192 + 64 * i;
            for (int x = tid; x < 512; x += 256) {
                int rr = x >> 3, c = (x & 7) << 3;
                int un = u0 + rr;
                int slot = un & 255;
                int grow = pbase0 + un; if (grow > P_) grow = P_;
                size_t psrc = (size_t)grow * F_ + h * DK_ + c;
                cp16(&PH[slot * 72 + c], g_Ph + psrc);
                cp16(&PL[slot * 72 + c], g_Pl + psrc);
            }
            asm volatile("cp.async.commit_group;");
        }
        if (tid < 64) MSK[tid] = (mask[b * T_ + s0 + tid] == 0) ? -3.0e38f : 0.f;
        if (i < 15) asm volatile("cp.async.wait_group 1;" ::: "memory");
        else        asm volatile("cp.async.wait_group 0;" ::: "memory");
        __syncthreads();

        const __nv_bfloat16* kh = KH + (i & 1) * 4608;
        const __nv_bfloat16* kl = KL + (i & 1) * 4608;
        const __nv_bfloat16* vh = VH + (i & 1) * 4608;
        const __nv_bfloat16* vl = VL + (i & 1) * 4608;
        const int off = (64 * i) & 255;

        // ---- G = qv_strip @ Pwin^T (banded BD; split-chain accumulate) ----
        {
            int prow = 112 - 16 * warp + (lane & 7);
            int psel = ((lane >> 3) & 1) << 3;
#pragma unroll
            for (int nt = 0; nt < 10; nt++) {
                float gA0 = 0.f, gA1 = 0.f, gA2 = 0.f, gA3 = 0.f;
                float gB0 = 0.f, gB1 = 0.f, gB2 = 0.f, gB3 = 0.f;
                int prw = (prow + nt * 8 + off) & 255;
#pragma unroll
                for (int kc = 0; kc < 4; kc++) {
                    unsigned p0, p1, q0, q1;
                    ldsm_x2(smem_u32(&PH[prw * 72 + kc * 16 + psel]), p0, p1);
                    ldsm_x2(smem_u32(&PL[prw * 72 + kc * 16 + psel]), q0, q1);
                    mma_bf16(gA0, gA1, gA2, gA3, qvh[kc][0], qvh[kc][1], qvh[kc][2], qvh[kc][3], p0, p1);
                    mma_bf16(gB0, gB1, gB2, gB3, qvh[kc][0], qvh[kc][1], qvh[kc][2], qvh[kc][3], q0, q1);
                    mma_bf16(gB0, gB1, gB2, gB3, qvl[kc][0], qvl[kc][1], qvl[kc][2], qvl[kc][3], p0, p1);
                }
                int gc = nt * 8 + 2 * tig;
                GSw[gid * 88 + gc] = gA0 + gB0;
                GSw[gid * 88 + gc + 1] = gA1 + gB1;
                GSw[(gid + 8) * 88 + gc] = gA2 + gB2;
                GSw[(gid + 8) * 88 + gc + 1] = gA3 + gB3;
            }
        }
        __syncwarp();

        // ---- S = qu @ K^T + band(G) + mask (split-chain accumulate) ----
        float sf[8][4];
        {
            int krow = lane & 7;
            int ksel = ((lane >> 3) & 1) << 3;
#pragma unroll
            for (int nt = 0; nt < 8; nt++) {
                float aA0 = 0.f, aA1 = 0.f, aA2 = 0.f, aA3 = 0.f;
                float aB0 = 0.f, aB1 = 0.f, aB2 = 0.f, aB3 = 0.f;
#pragma unroll
                for (int kc = 0; kc < 4; kc++) {
                    unsigned k0, k1, k2, k3;
                    ldsm_x2(smem_u32(&kh[(nt * 8 + krow) * 72 + kc * 16 + ksel]), k0, k1);
                    ldsm_x2(smem_u32(&kl[(nt * 8 + krow) * 72 + kc * 16 + ksel]), k2, k3);
                    mma_bf16(aA0, aA1, aA2, aA3, quh[kc][0], quh[kc][1], quh[kc][2], quh[kc][3], k0, k1);
                    mma_bf16(aB0, aB1, aB2, aB3, quh[kc][0], quh[kc][1], quh[kc][2], quh[kc][3], k2, k3);
                    mma_bf16(aB0, aB1, aB2, aB3, qul[kc][0], qul[kc][1], qul[kc][2], qul[kc][3], k0, k1);
                }
                int col = nt * 8 + 2 * tig;
                sf[nt][0] = aA0 + aB0 + GSw[gid * 88 + col - gid + 15] + MSK[col];
                sf[nt][1] = aA1 + aB1 + GSw[gid * 88 + col - gid + 16] + MSK[col + 1];
                sf[nt][2] = aA2 + aB2 + GSw[(gid + 8) * 88 + col - gid + 7] + MSK[col];
                sf[nt][3] = aA3 + aB3 + GSw[(gid + 8) * 88 + col - gid + 8] + MSK[col + 1];
            }
        }

        // ---- online softmax ----
        float mx0 = -1e30f, mx1 = -1e30f;
#pragma unroll
        for (int nt = 0; nt < 8; nt++) {
            mx0 = fmaxf(mx0, fmaxf(sf[nt][0], sf[nt][1]));
            mx1 = fmaxf(mx1, fmaxf(sf[nt][2], sf[nt][3]));
        }
        mx0 = fmaxf(mx0, __shfl_xor_sync(0xffffffffu, mx0, 1));
        mx0 = fmaxf(mx0, __shfl_xor_sync(0xffffffffu, mx0, 2));
        mx1 = fmaxf(mx1, __shfl_xor_sync(0xffffffffu, mx1, 1));
        mx1 = fmaxf(mx1, __shfl_xor_sync(0xffffffffu, mx1, 2));
        float mn0 = fmaxf(mr0, mx0), mn1 = fmaxf(mr1, mx1);
        float sc0 = __expf(mr0 - mn0), sc1 = __expf(mr1 - mn1);
        float su0 = 0.f, su1 = 0.f;
#pragma unroll
        for (int nt = 0; nt < 8; nt++) {
            sf[nt][0] = __expf(sf[nt][0] - mn0);
            sf[nt][1] = __expf(sf[nt][1] - mn0);
            sf[nt][2] = __expf(sf[nt][2] - mn1);
            sf[nt][3] = __expf(sf[nt][3] - mn1);
            su0 += sf[nt][0] + sf[nt][1];
            su1 += sf[nt][2] + sf[nt][3];
        }
        su0 += __shfl_xor_sync(0xffffffffu, su0, 1);
        su0 += __shfl_xor_sync(0xffffffffu, su0, 2);
        su1 += __shfl_xor_sync(0xffffffffu, su1, 1);
        su1 += __shfl_xor_sync(0xffffffffu, su1, 2);
        l0 = l0 * sc0 + su0;
        l1 = l1 * sc1 + su1;
        mr0 = mn0; mr1 = mn1;
#pragma unroll
        for (int nt = 0; nt < 8; nt++) {
            o[nt][0] *= sc0;  o[nt][1] *= sc0;
            o[nt][2] *= sc1;  o[nt][3] *= sc1;
            oL[nt][0] *= sc0; oL[nt][1] *= sc0;
            oL[nt][2] *= sc1; oL[nt][3] *= sc1;
        }

        // ---- O += P @ V (split: o = hh chain, oL = lo chains) ----
        {
            int vrow = lane & 7;
            int vsel = ((lane >> 3) & 1) << 3;
#pragma unroll
            for (int kc = 0; kc < 4; kc++) {
                unsigned ah[4], al[4];
                pack_hl(sf[2 * kc][0], sf[2 * kc][1], ah[0], al[0]);
                pack_hl(sf[2 * kc][2], sf[2 * kc][3], ah[1], al[1]);
                pack_hl(sf[2 * kc + 1][0], sf[2 * kc + 1][1], ah[2], al[2]);
                pack_hl(sf[2 * kc + 1][2], sf[2 * kc + 1][3], ah[3], al[3]);
#pragma unroll
                for (int nt = 0; nt < 8; nt++) {
                    unsigned v0, v1, w0, w1;
                    ldsm_x2(smem_u32(&vh[(nt * 8 + vrow) * 72 + kc * 16 + vsel]), v0, v1);
                    ldsm_x2(smem_u32(&vl[(nt * 8 + vrow) * 72 + kc * 16 + vsel]), w0, w1);
                    mma_bf16(o[nt][0], o[nt][1], o[nt][2], o[nt][3],
                             ah[0], ah[1], ah[2], ah[3], v0, v1);
                    mma_bf16(oL[nt][0], oL[nt][1], oL[nt][2], oL[nt][3],
                             ah[0], ah[1], ah[2], ah[3], w0, w1);
                    mma_bf16(oL[nt][0], oL[nt][1], oL[nt][2], oL[nt][3],
                             al[0], al[1], al[2], al[3], v0, v1);
                }
            }
        }
        __syncthreads();
    }

    // ---- epilogue ----
    float inv0 = (l0 > 0.f) ? 1.f / l0 : 0.f;
    float inv1 = (l1 > 0.f) ? 1.f / l1 : 0.f;
    int row0 = t0 + warp * 16 + gid;
#pragma unroll
    for (int nt = 0; nt < 8; nt++) {
        int colg = h * DK_ + nt * 8 + 2 * tig;
        float2 w0 = make_float2((o[nt][0] + oL[nt][0]) * inv0, (o[nt][1] + oL[nt][1]) * inv0);
        *(float2*)&g_ctx[((size_t)(b * T_ + row0)) * F_ + colg] = w0;
        float2 w1 = make_float2((o[nt][2] + oL[nt][2]) * inv1, (o[nt][3] + oL[nt][3]) * inv1);
        *(float2*)&g_ctx[((size_t)(b * T_ + row0 + 8)) * F_ + colg] = w1;
    }
}

// =====================================================================
extern "C" void kernel_launch(void* const* d_in, const int* in_sizes, int n_in,
                              void* d_out, int out_size)
{
    const float* query   = (const float*)d_in[0];
    const float* key_in  = (const float*)d_in[1];
    const float* value   = (const float*)d_in[2];
    const float* pos_emb = (const float*)d_in[3];
    const int*   mask    = (const int*)d_in[4];
    const float* Wq = (const float*)d_in[5];
    const float* bq = (const float*)d_in[6];
    const float* Wk = (const float*)d_in[7];
    const float* bk = (const float*)d_in[8];
    const float* Wv = (const float*)d_in[9];
    const float* bv = (const float*)d_in[10];
    const float* Wo = (const float*)d_in[11];
    const float* bo = (const float*)d_in[12];
    const float* Wp = (const float*)d_in[13];
    const float* pu = (const float*)d_in[14];
    const float* pv = (const float*)d_in[15];
    float* out = (float*)d_out;

    float *Qp, *Cp;
    __nv_bfloat16 *Khp, *Klp, *Vthp, *Vtlp, *Php, *Plp;
    cudaGetSymbolAddress((void**)&Qp,   g_Q);
    cudaGetSymbolAddress((void**)&Cp,   g_ctx);
    cudaGetSymbolAddress((void**)&Khp,  g_Kh);
    cudaGetSymbolAddress((void**)&Klp,  g_Kl);
    cudaGetSymbolAddress((void**)&Vthp, g_Vth);
    cudaGetSymbolAddress((void**)&Vtlp, g_Vtl);
    cudaGetSymbolAddress((void**)&Php,  g_Ph);
    cudaGetSymbolAddress((void**)&Plp,  g_Pl);

    cudaFuncSetAttribute(flash_kernel, cudaFuncAttributeMaxDynamicSharedMemorySize, FL_SMEM);

    // ---- all 4 input projections in ONE launch (grid.z = job id) ----
    GemmJobs pj;
    pj.j[0] = { query,   Wq, bq,      Qp,      nullptr, nullptr, B_ * T_, 0 };
    pj.j[1] = { key_in,  Wk, bk,      nullptr, Khp,     Klp,     B_ * T_, 1 };
    pj.j[2] = { value,   Wv, bv,      nullptr, Vthp,    Vtlp,    B_ * T_, 2 };
    pj.j[3] = { pos_emb, Wp, nullptr, nullptr, Php,     Plp,     P_,      1 };
    gemm_multi<<<dim3(4, 64, 4), 256>>>(pj);

    // fused attention (scores + rel-shift + softmax + AV), pipelined
    flash_kernel<<<dim3(8, B_ * H_), 256, FL_SMEM>>>(pu, pv, mask);

    // output projection
    GemmJobs oj;
    oj.j[0] = { Cp, Wo, bo, out, nullptr, nullptr, B_ * T_, 0 };
    oj.j[1] = oj.j[0]; oj.j[2] = oj.j[0]; oj.j[3] = oj.j[0];
    gemm_multi<<<dim3(4, 64, 1), 256>>>(oj);
}

// round 9
// speedup vs baseline: 1.1616x; 1.0027x over previous
#include <cuda_runtime.h>
#include <cuda_bf16.h>
#include <math.h>

#define B_ 8
#define T_ 1024
#define F_ 512
#define H_ 8
#define DK_ 64
#define P_ 2047

// -------- scratch (device globals; no allocations allowed) --------
__device__ float g_Q[(size_t)B_ * T_ * F_];                 // fp32 q proj
__device__ __nv_bfloat16 g_Kh[(size_t)B_ * T_ * F_];        // k hi
__device__ __nv_bfloat16 g_Kl[(size_t)B_ * T_ * F_];        // k lo
__device__ __nv_bfloat16 g_Vth[(size_t)B_ * H_ * DK_ * T_]; // v^T hi  [b,h,d,s]
__device__ __nv_bfloat16 g_Vtl[(size_t)B_ * H_ * DK_ * T_]; // v^T lo
__device__ __nv_bfloat16 g_Ph[(size_t)(P_ + 1) * F_];       // p hi (row 2047 spare)
__device__ __nv_bfloat16 g_Pl[(size_t)(P_ + 1) * F_];       // p lo
__device__ float g_ctx[(size_t)B_ * T_ * F_];

// =====================================================================
// Tensor-core helpers
// =====================================================================
__device__ __forceinline__ unsigned smem_u32(const void* p) {
    return (unsigned)__cvta_generic_to_shared(p);
}

__device__ __forceinline__ void ldsm_x4(unsigned addr, unsigned& r0, unsigned& r1,
                                        unsigned& r2, unsigned& r3) {
    asm volatile("ldmatrix.sync.aligned.m8n8.x4.shared.b16 {%0,%1,%2,%3}, [%4];"
                 : "=r"(r0), "=r"(r1), "=r"(r2), "=r"(r3) : "r"(addr));
}

__device__ __forceinline__ void ldsm_x2(unsigned addr, unsigned& r0, unsigned& r1) {
    asm volatile("ldmatrix.sync.aligned.m8n8.x2.shared.b16 {%0,%1}, [%2];"
                 : "=r"(r0), "=r"(r1) : "r"(addr));
}

__device__ __forceinline__ void mma_bf16(float& c0, float& c1, float& c2, float& c3,
                                         unsigned a0, unsigned a1, unsigned a2, unsigned a3,
                                         unsigned b0, unsigned b1) {
    asm volatile(
        "mma.sync.aligned.m16n8k16.row.col.f32.bf16.bf16.f32 "
        "{%0,%1,%2,%3},{%4,%5,%6,%7},{%8,%9},{%0,%1,%2,%3};"
        : "+f"(c0), "+f"(c1), "+f"(c2), "+f"(c3)
        : "r"(a0), "r"(a1), "r"(a2), "r"(a3), "r"(b0), "r"(b1));
}

__device__ __forceinline__ void split_hl(float x, __nv_bfloat16& h, __nv_bfloat16& l) {
    h = __float2bfloat16(x);
    l = __float2bfloat16(x - __bfloat162float(h));
}

__device__ __forceinline__ void pack_hl(float x0, float x1, unsigned& hi, unsigned& lo) {
    __nv_bfloat16 h0, l0, h1, l1;
    split_hl(x0, h0, l0);
    split_hl(x1, h1, l1);
    hi = ((unsigned)__bfloat16_as_ushort(h1) << 16) | (unsigned)__bfloat16_as_ushort(h0);
    lo = ((unsigned)__bfloat16_as_ushort(l1) << 16) | (unsigned)__bfloat16_as_ushort(l0);
}

__device__ __forceinline__ void cvt4(__nv_bfloat16* dh, __nv_bfloat16* dl, float4 v) {
    float f[4] = {v.x, v.y, v.z, v.w};
#pragma unroll
    for (int i = 0; i < 4; i++) split_hl(f[i], dh[i], dl[i]);
}

__device__ __forceinline__ void cp16(void* smem_dst, const void* gsrc) {
    unsigned d = smem_u32(smem_dst);
    asm volatile("cp.async.cg.shared.global [%0], [%1], 16;" :: "r"(d), "l"(gsrc));
}

// =====================================================================
// bf16x3 tensor-core NT GEMM, multi-job batched over grid.z.
// (exact R6 version — known good at 182us/46us)
// =====================================================================
#define BK_ 32
#define LDSA (BK_ + 8)
#define GN_ 512
#define GK_ 512

struct GemmJob {
    const float* A; const float* W; const float* bias;
    float* C; __nv_bfloat16* Ch; __nv_bfloat16* Cl;
    int M; int mode;
};
struct GemmJobs { GemmJob j[4]; };

__global__ void __launch_bounds__(256) gemm_multi(GemmJobs jobs)
{
    __shared__ __nv_bfloat16 Ah[128][LDSA], Al[128][LDSA];
    __shared__ __nv_bfloat16 Wh[128][LDSA], Wl[128][LDSA];

    const GemmJob job = jobs.j[blockIdx.z];
    const int M = job.M;
    const int m0 = blockIdx.y * 128;
    if (m0 >= M) return;
    const int n0 = blockIdx.x * 128;

    const float* __restrict__ A = job.A;
    const float* __restrict__ W = job.W;

    const int tid = threadIdx.x;
    const int lane = tid & 31;
    const int warp = tid >> 5;
    const int wm = warp & 1;
    const int wn = warp >> 1;

    const int arow = lane & 15;
    const int asel = (lane >> 4) << 3;
    const int bn_off = lane & 7;
    const int bsel = ((lane >> 3) & 1) << 3;

    float acc[4][4][4];
#pragma unroll
    for (int i = 0; i < 4; i++)
#pragma unroll
        for (int j = 0; j < 4; j++)
#pragma unroll
            for (int q = 0; q < 4; q++) acc[i][j][q] = 0.f;

    for (int k0 = 0; k0 < GK_; k0 += BK_) {
#pragma unroll
        for (int q = 0; q < 4; q++) {
            int idx = tid + q * 256;
            int row = idx >> 3;
            int col = (idx & 7) << 2;
            int gm = m0 + row; if (gm >= M) gm = M - 1;
            float4 a4 = *(const float4*)(A + (size_t)gm * GK_ + k0 + col);
            cvt4(&Ah[row][col], &Al[row][col], a4);
            int gn = n0 + row;
            float4 w4 = *(const float4*)(W + (size_t)gn * GK_ + k0 + col);
            cvt4(&Wh[row][col], &Wl[row][col], w4);
        }
        __syncthreads();

#pragma unroll
        for (int kk = 0; kk < 2; kk++) {
            const int kb = kk << 4;
            unsigned ah[4][4], al[4][4], bh[4][2], bl[4][2];
#pragma unroll
            for (int i = 0; i < 4; i++) {
                int r = wm * 64 + i * 16 + arow;
                ldsm_x4(smem_u32(&Ah[r][kb + asel]), ah[i][0], ah[i][1], ah[i][2], ah[i][3]);
                ldsm_x4(smem_u32(&Al[r][kb + asel]), al[i][0], al[i][1], al[i][2], al[i][3]);
            }
#pragma unroll
            for (int j = 0; j < 4; j++) {
                int n = wn * 32 + j * 8 + bn_off;
                ldsm_x2(smem_u32(&Wh[n][kb + bsel]), bh[j][0], bh[j][1]);
                ldsm_x2(smem_u32(&Wl[n][kb + bsel]), bl[j][0], bl[j][1]);
            }
#pragma unroll
            for (int i = 0; i < 4; i++)
#pragma unroll
                for (int j = 0; j < 4; j++) {
                    mma_bf16(acc[i][j][0], acc[i][j][1], acc[i][j][2], acc[i][j][3],
                             ah[i][0], ah[i][1], ah[i][2], ah[i][3], bh[j][0], bh[j][1]);
                    mma_bf16(acc[i][j][0], acc[i][j][1], acc[i][j][2], acc[i][j][3],
                             ah[i][0], ah[i][1], ah[i][2], ah[i][3], bl[j][0], bl[j][1]);
                    mma_bf16(acc[i][j][0], acc[i][j][1], acc[i][j][2], acc[i][j][3],
                             al[i][0], al[i][1], al[i][2], al[i][3], bh[j][0], bh[j][1]);
                }
        }
        __syncthreads();
    }

#pragma unroll
    for (int i = 0; i < 4; i++) {
        int mbase = m0 + wm * 64 + i * 16 + (lane >> 2);
#pragma unroll
        for (int j = 0; j < 4; j++) {
            int n = n0 + wn * 32 + j * 8 + (lane & 3) * 2;
            float bb0 = job.bias ? job.bias[n] : 0.f;
            float bb1 = job.bias ? job.bias[n + 1] : 0.f;
#pragma unroll
            for (int half = 0; half < 2; half++) {
                int m = mbase + half * 8;
                if (m >= M) continue;
                float v0 = acc[i][j][half * 2 + 0] + bb0;
                float v1 = acc[i][j][half * 2 + 1] + bb1;
                if (job.mode == 0) {
                    job.C[(size_t)m * GN_ + n] = v0;
                    job.C[(size_t)m * GN_ + n + 1] = v1;
                } else if (job.mode == 1) {
                    __nv_bfloat16 h0, l0, h1, l1;
                    split_hl(v0, h0, l0); split_hl(v1, h1, l1);
                    job.Ch[(size_t)m * GN_ + n] = h0; job.Cl[(size_t)m * GN_ + n] = l0;
                    job.Ch[(size_t)m * GN_ + n + 1] = h1; job.Cl[(size_t)m * GN_ + n + 1] = l1;
                } else {
                    int bb = m >> 10, ss = m & 1023;
#pragma unroll
                    for (int e = 0; e < 2; e++) {
                        int nn = n + e;
                        int hh = nn >> 6, dd = nn & 63;
                        size_t dst = (((size_t)(bb * H_ + hh) * DK_ + dd) * T_ + ss);
                        __nv_bfloat16 hv, lv;
                        split_hl(e ? v1 : v0, hv, lv);
                        job.Ch[dst] = hv; job.Cl[dst] = lv;
                    }
                }
            }
        }
    }
}

// =====================================================================
// Fused flash attention, software-pipelined with cp.async.
// R6 structure; this round: split MMA accumulation chains (2 independent
// accumulator sets per phase) to break accumulator RAW serialization.
// =====================================================================
#define FL_SMEM 192768

__global__ void __launch_bounds__(256) flash_kernel(
    const float* __restrict__ pu, const float* __restrict__ pv,
    const int* __restrict__ mask)
{
    extern __shared__ char sm[];
    __nv_bfloat16* KH = (__nv_bfloat16*)(sm);             // 2 x [64][72]
    __nv_bfloat16* KL = (__nv_bfloat16*)(sm + 18432);
    __nv_bfloat16* VH = (__nv_bfloat16*)(sm + 36864);     // 2 x [64 d][72 s]
    __nv_bfloat16* VL = (__nv_bfloat16*)(sm + 55296);
    __nv_bfloat16* PH = (__nv_bfloat16*)(sm + 73728);     // [256][72] circular
    __nv_bfloat16* PL = (__nv_bfloat16*)(sm + 110592);
    float* GS  = (float*)(sm + 147456);                   // [8 warps][16][88]
    float* MSK = (float*)(sm + 192512);                   // [64]
    // prologue aliases over the P region (dead before first P prefetch)
    __nv_bfloat16* QUH = (__nv_bfloat16*)(sm + 73728);    // [128][72]
    __nv_bfloat16* QUL = (__nv_bfloat16*)(sm + 92160);
    __nv_bfloat16* QVH = (__nv_bfloat16*)(sm + 110592);
    __nv_bfloat16* QVL = (__nv_bfloat16*)(sm + 129024);

    const int tid = threadIdx.x, lane = tid & 31, warp = tid >> 5;
    const int gid = lane >> 2, tig = lane & 3;
    const int bh = blockIdx.y, b = bh >> 3, h = bh & 7;
    const int t0 = blockIdx.x * 128;
    const int pbase0 = T_ - 1 - t0 - 127;   // >= 0

    // ---- phase 0: qu/qv hi-lo staging (scaled by 1/sqrt(DK)=0.125) ----
    for (int x = tid; x < 2048; x += 256) {
        int r = x >> 4, c = (x & 15) << 2;
        float4 q4 = *(const float4*)(g_Q + ((size_t)(b * T_ + t0 + r)) * F_ + h * DK_ + c);
        float4 u4 = *(const float4*)(pu + h * DK_ + c);
        float4 v4 = *(const float4*)(pv + h * DK_ + c);
        float qs[4] = {q4.x, q4.y, q4.z, q4.w};
        float us[4] = {u4.x, u4.y, u4.z, u4.w};
        float vs[4] = {v4.x, v4.y, v4.z, v4.w};
#pragma unroll
        for (int e = 0; e < 4; e++) {
            __nv_bfloat16 hh, ll;
            split_hl((qs[e] + us[e]) * 0.125f, hh, ll);
            QUH[r * 72 + c + e] = hh; QUL[r * 72 + c + e] = ll;
            split_hl((qs[e] + vs[e]) * 0.125f, hh, ll);
            QVH[r * 72 + c + e] = hh; QVL[r * 72 + c + e] = ll;
        }
    }
    __syncthreads();

    unsigned quh[4][4], qul[4][4], qvh[4][4], qvl[4][4];
    {
        int ar = warp * 16 + (lane & 15);
        int ac = (lane >> 4) << 3;
#pragma unroll
        for (int kc = 0; kc < 4; kc++) {
            ldsm_x4(smem_u32(&QUH[ar * 72 + kc * 16 + ac]), quh[kc][0], quh[kc][1], quh[kc][2], quh[kc][3]);
            ldsm_x4(smem_u32(&QUL[ar * 72 + kc * 16 + ac]), qul[kc][0], qul[kc][1], qul[kc][2], qul[kc][3]);
            ldsm_x4(smem_u32(&QVH[ar * 72 + kc * 16 + ac]), qvh[kc][0], qvh[kc][1], qvh[kc][2], qvh[kc][3]);
            ldsm_x4(smem_u32(&QVL[ar * 72 + kc * 16 + ac]), qvl[kc][0], qvl[kc][1], qvl[kc][2], qvl[kc][3]);
        }
    }
    __syncthreads();   // P region free from here on

    // ---- initial prefetch: tile 0 K/V (buf 0) + P rows [0,192) ----
    for (int x = tid; x < 512; x += 256) {
        int r = x >> 3, c = (x & 7) << 3;
        size_t ksrc = ((size_t)(b * T_ + r)) * F_ + h * DK_ + c;
        cp16(&KH[r * 72 + c], g_Kh + ksrc);
        cp16(&KL[r * 72 + c], g_Kl + ksrc);
        size_t vsrc = ((size_t)bh * DK_ + r) * T_ + c;
        cp16(&VH[r * 72 + c], g_Vth + vsrc);
        cp16(&VL[r * 72 + c], g_Vtl + vsrc);
    }
    for (int x = tid; x < 1536; x += 256) {
        int rr = x >> 3, c = (x & 7) << 3;
        int grow = pbase0 + rr; if (grow > P_) grow = P_;
        size_t psrc = (size_t)grow * F_ + h * DK_ + c;
        cp16(&PH[rr * 72 + c], g_Ph + psrc);
        cp16(&PL[rr * 72 + c], g_Pl + psrc);
    }
    asm volatile("cp.async.commit_group;");

    float o[8][4], oL[8][4];
#pragma unroll
    for (int nt = 0; nt < 8; nt++)
#pragma unroll
        for (int q = 0; q < 4; q++) { o[nt][q] = 0.f; oL[nt][q] = 0.f; }
    float mr0 = -1e30f, mr1 = -1e30f, l0 = 0.f, l1 = 0.f;
    float* GSw = GS + warp * (16 * 88);

    for (int i = 0; i < 16; i++) {
        const int s0 = i * 64;

        // ---- prefetch tile i+1 ----
        if (i < 15) {
            __nv_bfloat16* kh = KH + ((i + 1) & 1) * 4608;
            __nv_bfloat16* kl = KL + ((i + 1) & 1) * 4608;
            __nv_bfloat16* vh = VH + ((i + 1) & 1) * 4608;
            __nv_bfloat16* vl = VL + ((i + 1) & 1) * 4608;
            int s0n = s0 + 64;
            for (int x = tid; x < 512; x += 256) {
                int r = x >> 3, c = (x & 7) << 3;
                size_t ksrc = ((size_t)(b * T_ + s0n + r)) * F_ + h * DK_ + c;
                cp16(&kh[r * 72 + c], g_Kh + ksrc);
                cp16(&kl[r * 72 + c], g_Kl + ksrc);
                size_t vsrc = ((size_t)bh * DK_ + r) * T_ + s0n + c;
                cp16(&vh[r * 72 + c], g_Vth + vsrc);
                cp16(&vl[r * 72 + c], g_Vtl + vsrc);
            }
            int u0 = 192 + 64 * i;
            for (int x = tid; x < 512; x += 256) {
                int rr = x >> 3, c = (x & 7) << 3;
                int un = u0 + rr;
                int slot = un & 255;
                int grow = pbase0 + un; if (grow > P_) grow = P_;
                size_t psrc = (size_t)grow * F_ + h * DK_ + c;
                cp16(&PH[slot * 72 + c], g_Ph + psrc);
                cp16(&PL[slot * 72 + c], g_Pl + psrc);
            }
            asm volatile("cp.async.commit_group;");
        }
        if (tid < 64) MSK[tid] = (mask[b * T_ + s0 + tid] == 0) ? -3.0e38f : 0.f;
        if (i < 15) asm volatile("cp.async.wait_group 1;" ::: "memory");
        else        asm volatile("cp.async.wait_group 0;" ::: "memory");
        __syncthreads();

        const __nv_bfloat16* kh = KH + (i & 1) * 4608;
        const __nv_bfloat16* kl = KL + (i & 1) * 4608;
        const __nv_bfloat16* vh = VH + (i & 1) * 4608;
        const __nv_bfloat16* vl = VL + (i & 1) * 4608;
        const int off = (64 * i) & 255;

        // ---- G = qv_strip @ Pwin^T (banded BD; split-chain accumulate) ----
        {
            int prow = 112 - 16 * warp + (lane & 7);
            int psel = ((lane >> 3) & 1) << 3;
#pragma unroll
            for (int nt = 0; nt < 10; nt++) {
                float gA0 = 0.f, gA1 = 0.f, gA2 = 0.f, gA3 = 0.f;
                float gB0 = 0.f, gB1 = 0.f, gB2 = 0.f, gB3 = 0.f;
                int prw = (prow + nt * 8 + off) & 255;
#pragma unroll
                for (int kc = 0; kc < 4; kc++) {
                    unsigned p0, p1, q0, q1;
                    ldsm_x2(smem_u32(&PH[prw * 72 + kc * 16 + psel]), p0, p1);
                    ldsm_x2(smem_u32(&PL[prw * 72 + kc * 16 + psel]), q0, q1);
                    mma_bf16(gA0, gA1, gA2, gA3, qvh[kc][0], qvh[kc][1], qvh[kc][2], qvh[kc][3], p0, p1);
                    mma_bf16(gB0, gB1, gB2, gB3, qvh[kc][0], qvh[kc][1], qvh[kc][2], qvh[kc][3], q0, q1);
                    mma_bf16(gB0, gB1, gB2, gB3, qvl[kc][0], qvl[kc][1], qvl[kc][2], qvl[kc][3], p0, p1);
                }
                int gc = nt * 8 + 2 * tig;
                GSw[gid * 88 + gc] = gA0 + gB0;
                GSw[gid * 88 + gc + 1] = gA1 + gB1;
                GSw[(gid + 8) * 88 + gc] = gA2 + gB2;
                GSw[(gid + 8) * 88 + gc + 1] = gA3 + gB3;
            }
        }
        __syncwarp();

        // ---- S = qu @ K^T + band(G) + mask (split-chain accumulate) ----
        float sf[8][4];
        {
            int krow = lane & 7;
            int ksel = ((lane >> 3) & 1) << 3;
#pragma unroll
            for (int nt = 0; nt < 8; nt++) {
                float aA0 = 0.f, aA1 = 0.f, aA2 = 0.f, aA3 = 0.f;
                float aB0 = 0.f, aB1 = 0.f, aB2 = 0.f, aB3 = 0.f;
#pragma unroll
                for (int kc = 0; kc < 4; kc++) {
                    unsigned k0, k1, k2, k3;
                    ldsm_x2(smem_u32(&kh[(nt * 8 + krow) * 72 + kc * 16 + ksel]), k0, k1);
                    ldsm_x2(smem_u32(&kl[(nt * 8 + krow) * 72 + kc * 16 + ksel]), k2, k3);
                    mma_bf16(aA0, aA1, aA2, aA3, quh[kc][0], quh[kc][1], quh[kc][2], quh[kc][3], k0, k1);
                    mma_bf16(aB0, aB1, aB2, aB3, quh[kc][0], quh[kc][1], quh[kc][2], quh[kc][3], k2, k3);
                    mma_bf16(aB0, aB1, aB2, aB3, qul[kc][0], qul[kc][1], qul[kc][2], qul[kc][3], k0, k1);
                }
                int col = nt * 8 + 2 * tig;
                sf[nt][0] = aA0 + aB0 + GSw[gid * 88 + col - gid + 15] + MSK[col];
                sf[nt][1] = aA1 + aB1 + GSw[gid * 88 + col - gid + 16] + MSK[col + 1];
                sf[nt][2] = aA2 + aB2 + GSw[(gid + 8) * 88 + col - gid + 7] + MSK[col];
                sf[nt][3] = aA3 + aB3 + GSw[(gid + 8) * 88 + col - gid + 8] + MSK[col + 1];
            }
        }

        // ---- online softmax ----
        float mx0 = -1e30f, mx1 = -1e30f;
#pragma unroll
        for (int nt = 0; nt < 8; nt++) {
            mx0 = fmaxf(mx0, fmaxf(sf[nt][0], sf[nt][1]));
            mx1 = fmaxf(mx1, fmaxf(sf[nt][2], sf[nt][3]));
        }
        mx0 = fmaxf(mx0, __shfl_xor_sync(0xffffffffu, mx0, 1));
        mx0 = fmaxf(mx0, __shfl_xor_sync(0xffffffffu, mx0, 2));
        mx1 = fmaxf(mx1, __shfl_xor_sync(0xffffffffu, mx1, 1));
        mx1 = fmaxf(mx1, __shfl_xor_sync(0xffffffffu, mx1, 2));
        float mn0 = fmaxf(mr0, mx0), mn1 = fmaxf(mr1, mx1);
        float sc0 = __expf(mr0 - mn0), sc1 = __expf(mr1 - mn1);
        float su0 = 0.f, su1 = 0.f;
#pragma unroll
        for (int nt = 0; nt < 8; nt++) {
            sf[nt][0] = __expf(sf[nt][0] - mn0);
            sf[nt][1] = __expf(sf[nt][1] - mn0);
            sf[nt][2] = __expf(sf[nt][2] - mn1);
            sf[nt][3] = __expf(sf[nt][3] - mn1);
            su0 += sf[nt][0] + sf[nt][1];
            su1 += sf[nt][2] + sf[nt][3];
        }
        su0 += __shfl_xor_sync(0xffffffffu, su0, 1);
        su0 += __shfl_xor_sync(0xffffffffu, su0, 2);
        su1 += __shfl_xor_sync(0xffffffffu, su1, 1);
        su1 += __shfl_xor_sync(0xffffffffu, su1, 2);
        l0 = l0 * sc0 + su0;
        l1 = l1 * sc1 + su1;
        mr0 = mn0; mr1 = mn1;
#pragma unroll
        for (int nt = 0; nt < 8; nt++) {
            o[nt][0] *= sc0;  o[nt][1] *= sc0;
            o[nt][2] *= sc1;  o[nt][3] *= sc1;
            oL[nt][0] *= sc0; oL[nt][1] *= sc0;
            oL[nt][2] *= sc1; oL[nt][3] *= sc1;
        }

        // ---- O += P @ V (split: o = hh chain, oL = lo chains) ----
        {
            int vrow = lane & 7;
            int vsel = ((lane >> 3) & 1) << 3;
#pragma unroll
            for (int kc = 0; kc < 4; kc++) {
                unsigned ah[4], al[4];
                pack_hl(sf[2 * kc][0], sf[2 * kc][1], ah[0], al[0]);
                pack_hl(sf[2 * kc][2], sf[2 * kc][3], ah[1], al[1]);
                pack_hl(sf[2 * kc + 1][0], sf[2 * kc + 1][1], ah[2], al[2]);
                pack_hl(sf[2 * kc + 1][2], sf[2 * kc + 1][3], ah[3], al[3]);
#pragma unroll
                for (int nt = 0; nt < 8; nt++) {
                    unsigned v0, v1, w0, w1;
                    ldsm_x2(smem_u32(&vh[(nt * 8 + vrow) * 72 + kc * 16 + vsel]), v0, v1);
                    ldsm_x2(smem_u32(&vl[(nt * 8 + vrow) * 72 + kc * 16 + vsel]), w0, w1);
                    mma_bf16(o[nt][0], o[nt][1], o[nt][2], o[nt][3],
                             ah[0], ah[1], ah[2], ah[3], v0, v1);
                    mma_bf16(oL[nt][0], oL[nt][1], oL[nt][2], oL[nt][3],
                             ah[0], ah[1], ah[2], ah[3], w0, w1);
                    mma_bf16(oL[nt][0], oL[nt][1], oL[nt][2], oL[nt][3],
                             al[0], al[1], al[2], al[3], v0, v1);
                }
            }
        }
        __syncthreads();
    }

    // ---- epilogue ----
    float inv0 = (l0 > 0.f) ? 1.f / l0 : 0.f;
    float inv1 = (l1 > 0.f) ? 1.f / l1 : 0.f;
    int row0 = t0 + warp * 16 + gid;
#pragma unroll
    for (int nt = 0; nt < 8; nt++) {
        int colg = h * DK_ + nt * 8 + 2 * tig;
        float2 w0 = make_float2((o[nt][0] + oL[nt][0]) * inv0, (o[nt][1] + oL[nt][1]) * inv0);
        *(float2*)&g_ctx[((size_t)(b * T_ + row0)) * F_ + colg] = w0;
        float2 w1 = make_float2((o[nt][2] + oL[nt][2]) * inv1, (o[nt][3] + oL[nt][3]) * inv1);
        *(float2*)&g_ctx[((size_t)(b * T_ + row0 + 8)) * F_ + colg] = w1;
    }
}

// =====================================================================
extern "C" void kernel_launch(void* const* d_in, const int* in_sizes, int n_in,
                              void* d_out, int out_size)
{
    const float* query   = (const float*)d_in[0];
    const float* key_in  = (const float*)d_in[1];
    const float* value   = (const float*)d_in[2];
    const float* pos_emb = (const float*)d_in[3];
    const int*   mask    = (const int*)d_in[4];
    const float* Wq = (const float*)d_in[5];
    const float* bq = (const float*)d_in[6];
    const float* Wk = (const float*)d_in[7];
    const float* bk = (const float*)d_in[8];
    const float* Wv = (const float*)d_in[9];
    const float* bv = (const float*)d_in[10];
    const float* Wo = (const float*)d_in[11];
    const float* bo = (const float*)d_in[12];
    const float* Wp = (const float*)d_in[13];
    const float* pu = (const float*)d_in[14];
    const float* pv = (const float*)d_in[15];
    float* out = (float*)d_out;

    float *Qp, *Cp;
    __nv_bfloat16 *Khp, *Klp, *Vthp, *Vtlp, *Php, *Plp;
    cudaGetSymbolAddress((void**)&Qp,   g_Q);
    cudaGetSymbolAddress((void**)&Cp,   g_ctx);
    cudaGetSymbolAddress((void**)&Khp,  g_Kh);
    cudaGetSymbolAddress((void**)&Klp,  g_Kl);
    cudaGetSymbolAddress((void**)&Vthp, g_Vth);
    cudaGetSymbolAddress((void**)&Vtlp, g_Vtl);
    cudaGetSymbolAddress((void**)&Php,  g_Ph);
    cudaGetSymbolAddress((void**)&Plp,  g_Pl);

    cudaFuncSetAttribute(flash_kernel, cudaFuncAttributeMaxDynamicSharedMemorySize, FL_SMEM);

    // ---- all 4 input projections in ONE launch (grid.z = job id) ----
    GemmJobs pj;
    pj.j[0] = { query,   Wq, bq,      Qp,      nullptr, nullptr, B_ * T_, 0 };
    pj.j[1] = { key_in,  Wk, bk,      nullptr, Khp,     Klp,     B_ * T_, 1 };
    pj.j[2] = { value,   Wv, bv,      nullptr, Vthp,    Vtlp,    B_ * T_, 2 };
    pj.j[3] = { pos_emb, Wp, nullptr, nullptr, Php,     Plp,     P_,      1 };
    gemm_multi<<<dim3(4, 64, 4), 256>>>(pj);

    // fused attention (scores + rel-shift + softmax + AV), pipelined
    flash_kernel<<<dim3(8, B_ * H_), 256, FL_SMEM>>>(pu, pv, mask);

    // output projection
    GemmJobs oj;
    oj.j[0] = { Cp, Wo, bo, out, nullptr, nullptr, B_ * T_, 0 };
    oj.j[1] = oj.j[0]; oj.j[2] = oj.j[0]; oj.j[3] = oj.j[0];
    gemm_multi<<<dim3(4, 64, 1), 256>>>(oj);
}

// round 11
// speedup vs baseline: 1.4352x; 1.2356x over previous
#include <cuda_runtime.h>
#include <cuda_bf16.h>
#include <cuda_fp16.h>
#include <math.h>

#define B_ 8
#define T_ 1024
#define F_ 512
#define H_ 8
#define DK_ 64
#define P_ 2047

// -------- scratch (device globals; no allocations allowed) --------
__device__ float g_Q[(size_t)B_ * T_ * F_];                 // fp32 q proj
__device__ __half g_Kf[(size_t)B_ * T_ * F_];               // k fp16 (scores)
__device__ __nv_bfloat16 g_Vth[(size_t)B_ * H_ * DK_ * T_]; // v^T hi  [b,h,d,s]
__device__ __nv_bfloat16 g_Vtl[(size_t)B_ * H_ * DK_ * T_]; // v^T lo
__device__ __half g_Pf[(size_t)(P_ + 1) * F_];              // p fp16 (row 2047 spare=0)
__device__ float g_ctx[(size_t)B_ * T_ * F_];

// =====================================================================
// Helpers
// =====================================================================
__device__ __forceinline__ unsigned smem_u32(const void* p) {
    return (unsigned)__cvta_generic_to_shared(p);
}
__device__ __forceinline__ void ldsm_x4(unsigned addr, unsigned& r0, unsigned& r1,
                                        unsigned& r2, unsigned& r3) {
    asm volatile("ldmatrix.sync.aligned.m8n8.x4.shared.b16 {%0,%1,%2,%3}, [%4];"
                 : "=r"(r0), "=r"(r1), "=r"(r2), "=r"(r3) : "r"(addr));
}
__device__ __forceinline__ void ldsm_x2(unsigned addr, unsigned& r0, unsigned& r1) {
    asm volatile("ldmatrix.sync.aligned.m8n8.x2.shared.b16 {%0,%1}, [%2];"
                 : "=r"(r0), "=r"(r1) : "r"(addr));
}
__device__ __forceinline__ void mma_bf16(float& c0, float& c1, float& c2, float& c3,
                                         unsigned a0, unsigned a1, unsigned a2, unsigned a3,
                                         unsigned b0, unsigned b1) {
    asm volatile(
        "mma.sync.aligned.m16n8k16.row.col.f32.bf16.bf16.f32 "
        "{%0,%1,%2,%3},{%4,%5,%6,%7},{%8,%9},{%0,%1,%2,%3};"
        : "+f"(c0), "+f"(c1), "+f"(c2), "+f"(c3)
        : "r"(a0), "r"(a1), "r"(a2), "r"(a3), "r"(b0), "r"(b1));
}
__device__ __forceinline__ void mma_fp16(float& c0, float& c1, float& c2, float& c3,
                                         unsigned a0, unsigned a1, unsigned a2, unsigned a3,
                                         unsigned b0, unsigned b1) {
    asm volatile(
        "mma.sync.aligned.m16n8k16.row.col.f32.f16.f16.f32 "
        "{%0,%1,%2,%3},{%4,%5,%6,%7},{%8,%9},{%0,%1,%2,%3};"
        : "+f"(c0), "+f"(c1), "+f"(c2), "+f"(c3)
        : "r"(a0), "r"(a1), "r"(a2), "r"(a3), "r"(b0), "r"(b1));
}
__device__ __forceinline__ void split_hl(float x, __nv_bfloat16& h, __nv_bfloat16& l) {
    h = __float2bfloat16(x);
    l = __float2bfloat16(x - __bfloat162float(h));
}
__device__ __forceinline__ void pack_hl(float x0, float x1, unsigned& hi, unsigned& lo) {
    __nv_bfloat16 h0, l0, h1, l1;
    split_hl(x0, h0, l0);
    split_hl(x1, h1, l1);
    hi = ((unsigned)__bfloat16_as_ushort(h1) << 16) | (unsigned)__bfloat16_as_ushort(h0);
    lo = ((unsigned)__bfloat16_as_ushort(l1) << 16) | (unsigned)__bfloat16_as_ushort(l0);
}
__device__ __forceinline__ void cvt4(__nv_bfloat16* dh, __nv_bfloat16* dl, float4 v) {
    float f[4] = {v.x, v.y, v.z, v.w};
#pragma unroll
    for (int i = 0; i < 4; i++) split_hl(f[i], dh[i], dl[i]);
}
__device__ __forceinline__ void cp16(void* smem_dst, const void* gsrc) {
    unsigned d = smem_u32(smem_dst);
    asm volatile("cp.async.cg.shared.global [%0], [%1], 16;" :: "r"(d), "l"(gsrc));
}

// =====================================================================
// bf16x3 tensor-core NT GEMM, multi-job batched over grid.z.
// mode 0: fp32 -> C. mode 1: fp16 single plane -> (half*)Ch.
// mode 2: bf16 hi/lo transposed per-head -> Ch,Cl.
// =====================================================================
#define BK_ 32
#define LDSA (BK_ + 8)
#define GN_ 512
#define GK_ 512

struct GemmJob {
    const float* A; const float* W; const float* bias;
    float* C; __nv_bfloat16* Ch; __nv_bfloat16* Cl;
    int M; int mode;
};
struct GemmJobs { GemmJob j[4]; };

__global__ void __launch_bounds__(256) gemm_multi(GemmJobs jobs)
{
    __shared__ __nv_bfloat16 Ah[128][LDSA], Al[128][LDSA];
    __shared__ __nv_bfloat16 Wh[128][LDSA], Wl[128][LDSA];

    const GemmJob job = jobs.j[blockIdx.z];
    const int M = job.M;
    const int m0 = blockIdx.y * 128;
    if (m0 >= M) return;
    const int n0 = blockIdx.x * 128;

    const float* __restrict__ A = job.A;
    const float* __restrict__ W = job.W;

    const int tid = threadIdx.x;
    const int lane = tid & 31;
    const int warp = tid >> 5;
    const int wm = warp & 1;
    const int wn = warp >> 1;

    const int arow = lane & 15;
    const int asel = (lane >> 4) << 3;
    const int bn_off = lane & 7;
    const int bsel = ((lane >> 3) & 1) << 3;

    float acc[4][4][4];
#pragma unroll
    for (int i = 0; i < 4; i++)
#pragma unroll
        for (int j = 0; j < 4; j++)
#pragma unroll
            for (int q = 0; q < 4; q++) acc[i][j][q] = 0.f;

    for (int k0 = 0; k0 < GK_; k0 += BK_) {
#pragma unroll
        for (int q = 0; q < 4; q++) {
            int idx = tid + q * 256;
            int row = idx >> 3;
            int col = (idx & 7) << 2;
            int gm = m0 + row; if (gm >= M) gm = M - 1;
            float4 a4 = *(const float4*)(A + (size_t)gm * GK_ + k0 + col);
            cvt4(&Ah[row][col], &Al[row][col], a4);
            int gn = n0 + row;
            float4 w4 = *(const float4*)(W + (size_t)gn * GK_ + k0 + col);
            cvt4(&Wh[row][col], &Wl[row][col], w4);
        }
        __syncthreads();

#pragma unroll
        for (int kk = 0; kk < 2; kk++) {
            const int kb = kk << 4;
            unsigned ah[4][4], al[4][4], bh[4][2], bl[4][2];
#pragma unroll
            for (int i = 0; i < 4; i++) {
                int r = wm * 64 + i * 16 + arow;
                ldsm_x4(smem_u32(&Ah[r][kb + asel]), ah[i][0], ah[i][1], ah[i][2], ah[i][3]);
                ldsm_x4(smem_u32(&Al[r][kb + asel]), al[i][0], al[i][1], al[i][2], al[i][3]);
            }
#pragma unroll
            for (int j = 0; j < 4; j++) {
                int n = wn * 32 + j * 8 + bn_off;
                ldsm_x2(smem_u32(&Wh[n][kb + bsel]), bh[j][0], bh[j][1]);
                ldsm_x2(smem_u32(&Wl[n][kb + bsel]), bl[j][0], bl[j][1]);
            }
#pragma unroll
            for (int i = 0; i < 4; i++)
#pragma unroll
                for (int j = 0; j < 4; j++) {
                    mma_bf16(acc[i][j][0], acc[i][j][1], acc[i][j][2], acc[i][j][3],
                             ah[i][0], ah[i][1], ah[i][2], ah[i][3], bh[j][0], bh[j][1]);
                    mma_bf16(acc[i][j][0], acc[i][j][1], acc[i][j][2], acc[i][j][3],
                             ah[i][0], ah[i][1], ah[i][2], ah[i][3], bl[j][0], bl[j][1]);
                    mma_bf16(acc[i][j][0], acc[i][j][1], acc[i][j][2], acc[i][j][3],
                             al[i][0], al[i][1], al[i][2], al[i][3], bh[j][0], bh[j][1]);
                }
        }
        __syncthreads();
    }

#pragma unroll
    for (int i = 0; i < 4; i++) {
        int mbase = m0 + wm * 64 + i * 16 + (lane >> 2);
#pragma unroll
        for (int j = 0; j < 4; j++) {
            int n = n0 + wn * 32 + j * 8 + (lane & 3) * 2;
            float bb0 = job.bias ? job.bias[n] : 0.f;
            float bb1 = job.bias ? job.bias[n + 1] : 0.f;
#pragma unroll
            for (int half = 0; half < 2; half++) {
                int m = mbase + half * 8;
                if (m >= M) continue;
                float v0 = acc[i][j][half * 2 + 0] + bb0;
                float v1 = acc[i][j][half * 2 + 1] + bb1;
                if (job.mode == 0) {
                    job.C[(size_t)m * GN_ + n] = v0;
                    job.C[(size_t)m * GN_ + n + 1] = v1;
                } else if (job.mode == 1) {
                    __half2 hv = __floats2half2_rn(v0, v1);
                    *(__half2*)((__half*)job.Ch + (size_t)m * GN_ + n) = hv;
                } else {
                    int bb = m >> 10, ss = m & 1023;
#pragma unroll
                    for (int e = 0; e < 2; e++) {
                        int nn = n + e;
                        int hh = nn >> 6, dd = nn & 63;
                        size_t dst = (((size_t)(bb * H_ + hh) * DK_ + dd) * T_ + ss);
                        __nv_bfloat16 hv, lv;
                        split_hl(e ? v1 : v0, hv, lv);
                        job.Ch[dst] = hv; job.Cl[dst] = lv;
                    }
                }
            }
        }
    }
}

// =====================================================================
// Fused flash attention. Scores (AC + banded BD) via single fp16 MMAs;
// AV via bf16x3. cp.async pipelined, 8 warps, 128 t-rows/block.
// =====================================================================
#define FL_SMEM 137472

__global__ void __launch_bounds__(256) flash_kernel(
    const float* __restrict__ pu, const float* __restrict__ pv,
    const int* __restrict__ mask)
{
    extern __shared__ char sm[];
    __half* KF = (__half*)(sm);                           // 2 x [64][72]
    __nv_bfloat16* VH = (__nv_bfloat16*)(sm + 18432);     // 2 x [64 d][72 s]
    __nv_bfloat16* VL = (__nv_bfloat16*)(sm + 36864);
    __half* PF = (__half*)(sm + 55296);                   // [256][72] circular
    float* GS  = (float*)(sm + 92160);                    // [8 warps][16][88]
    float* MSK = (float*)(sm + 137216);                   // [64]
    // prologue aliases over the PF region (dead before first P prefetch)
    __half* QUF = (__half*)(sm + 55296);                  // [128][72]
    __half* QVF = (__half*)(sm + 73728);

    const int tid = threadIdx.x, lane = tid & 31, warp = tid >> 5;
    const int gid = lane >> 2, tig = lane & 3;
    const int bh = blockIdx.y, b = bh >> 3, h = bh & 7;
    const int t0 = blockIdx.x * 128;
    const int pbase0 = T_ - 1 - t0 - 127;   // >= 0

    // ---- phase 0: qu/qv fp16 staging (scaled by 1/sqrt(DK)=0.125) ----
    for (int x = tid; x < 2048; x += 256) {
        int r = x >> 4, c = (x & 15) << 2;
        float4 q4 = *(const float4*)(g_Q + ((size_t)(b * T_ + t0 + r)) * F_ + h * DK_ + c);
        float4 u4 = *(const float4*)(pu + h * DK_ + c);
        float4 v4 = *(const float4*)(pv + h * DK_ + c);
        float qs[4] = {q4.x, q4.y, q4.z, q4.w};
        float us[4] = {u4.x, u4.y, u4.z, u4.w};
        float vs[4] = {v4.x, v4.y, v4.z, v4.w};
#pragma unroll
        for (int e = 0; e < 4; e++) {
            QUF[r * 72 + c + e] = __float2half((qs[e] + us[e]) * 0.125f);
            QVF[r * 72 + c + e] = __float2half((qs[e] + vs[e]) * 0.125f);
        }
    }
    __syncthreads();

    unsigned quf[4][4], qvf[4][4];
    {
        int ar = warp * 16 + (lane & 15);
        int ac = (lane >> 4) << 3;
#pragma unroll
        for (int kc = 0; kc < 4; kc++) {
            ldsm_x4(smem_u32(&QUF[ar * 72 + kc * 16 + ac]), quf[kc][0], quf[kc][1], quf[kc][2], quf[kc][3]);
            ldsm_x4(smem_u32(&QVF[ar * 72 + kc * 16 + ac]), qvf[kc][0], qvf[kc][1], qvf[kc][2], qvf[kc][3]);
        }
    }
    __syncthreads();   // PF region free from here on

    // ---- initial prefetch: tile 0 K/V (buf 0) + P rows [0,192) ----
    for (int x = tid; x < 512; x += 256) {
        int r = x >> 3, c = (x & 7) << 3;
        size_t ksrc = ((size_t)(b * T_ + r)) * F_ + h * DK_ + c;
        cp16(&KF[r * 72 + c], g_Kf + ksrc);
        size_t vsrc = ((size_t)bh * DK_ + r) * T_ + c;
        cp16(&VH[r * 72 + c], g_Vth + vsrc);
        cp16(&VL[r * 72 + c], g_Vtl + vsrc);
    }
    for (int x = tid; x < 1536; x += 256) {
        int rr = x >> 3, c = (x & 7) << 3;
        int grow = pbase0 + rr; if (grow > P_) grow = P_;
        cp16(&PF[rr * 72 + c], g_Pf + (size_t)grow * F_ + h * DK_ + c);
    }
    asm volatile("cp.async.commit_group;");

    float o[8][4], oL[8][4];
#pragma unroll
    for (int nt = 0; nt < 8; nt++)
#pragma unroll
        for (int q = 0; q < 4; q++) { o[nt][q] = 0.f; oL[nt][q] = 0.f; }
    float mr0 = -1e30f, mr1 = -1e30f, l0 = 0.f, l1 = 0.f;
    float* GSw = GS + warp * (16 * 88);

    for (int i = 0; i < 16; i++) {
        const int s0 = i * 64;

        // ---- prefetch tile i+1 ----
        if (i < 15) {
            __half* kf = KF + ((i + 1) & 1) * 4608;
            __nv_bfloat16* vh = VH + ((i + 1) & 1) * 4608;
            __nv_bfloat16* vl = VL + ((i + 1) & 1) * 4608;
            int s0n = s0 + 64;
            for (int x = tid; x < 512; x += 256) {
                int r = x >> 3, c = (x & 7) << 3;
                size_t ksrc = ((size_t)(b * T_ + s0n + r)) * F_ + h * DK_ + c;
                cp16(&kf[r * 72 + c], g_Kf + ksrc);
                size_t vsrc = ((size_t)bh * DK_ + r) * T_ + s0n + c;
                cp16(&vh[r * 72 + c], g_Vth + vsrc);
                cp16(&vl[r * 72 + c], g_Vtl + vsrc);
            }
            int u0 = 192 + 64 * i;
            for (int x = tid; x < 512; x += 256) {
                int rr = x >> 3, c = (x & 7) << 3;
                int un = u0 + rr;
                int slot = un & 255;
                int grow = pbase0 + un; if (grow > P_) grow = P_;
                cp16(&PF[slot * 72 + c], g_Pf + (size_t)grow * F_ + h * DK_ + c);
            }
            asm volatile("cp.async.commit_group;");
        }
        if (tid < 64) MSK[tid] = (mask[b * T_ + s0 + tid] == 0) ? -3.0e38f : 0.f;
        if (i < 15) asm volatile("cp.async.wait_group 1;" ::: "memory");
        else        asm volatile("cp.async.wait_group 0;" ::: "memory");
        __syncthreads();

        const __half* kf = KF + (i & 1) * 4608;
        const __nv_bfloat16* vh = VH + (i & 1) * 4608;
        const __nv_bfloat16* vl = VL + (i & 1) * 4608;
        const int off = (64 * i) & 255;

        // ---- G = qv_strip @ Pwin^T (banded BD, fp16 single, 2 chains) ----
        {
            int prow = 112 - 16 * warp + (lane & 7);
            int psel = ((lane >> 3) & 1) << 3;
#pragma unroll
            for (int nt = 0; nt < 10; nt++) {
                float gA0 = 0.f, gA1 = 0.f, gA2 = 0.f, gA3 = 0.f;
                float gB0 = 0.f, gB1 = 0.f, gB2 = 0.f, gB3 = 0.f;
                int prw = (prow + nt * 8 + off) & 255;
#pragma unroll
                for (int kc = 0; kc < 4; kc += 2) {
                    unsigned p0, p1, p2, p3;
                    ldsm_x2(smem_u32(&PF[prw * 72 + kc * 16 + psel]), p0, p1);
                    ldsm_x2(smem_u32(&PF[prw * 72 + (kc + 1) * 16 + psel]), p2, p3);
                    mma_fp16(gA0, gA1, gA2, gA3, qvf[kc][0], qvf[kc][1], qvf[kc][2], qvf[kc][3], p0, p1);
                    mma_fp16(gB0, gB1, gB2, gB3, qvf[kc + 1][0], qvf[kc + 1][1], qvf[kc + 1][2], qvf[kc + 1][3], p2, p3);
                }
                int gc = nt * 8 + 2 * tig;
                GSw[gid * 88 + gc] = gA0 + gB0;
                GSw[gid * 88 + gc + 1] = gA1 + gB1;
                GSw[(gid + 8) * 88 + gc] = gA2 + gB2;
                GSw[(gid + 8) * 88 + gc + 1] = gA3 + gB3;
            }
        }
        __syncwarp();

        // ---- S = qu @ K^T + band(G) + mask (fp16 single, 2 chains) ----
        float sf[8][4];
        {
            int krow = lane & 7;
            int ksel = ((lane >> 3) & 1) << 3;
#pragma unroll
            for (int nt = 0; nt < 8; nt++) {
                float aA0 = 0.f, aA1 = 0.f, aA2 = 0.f, aA3 = 0.f;
                float aB0 = 0.f, aB1 = 0.f, aB2 = 0.f, aB3 = 0.f;
#pragma unroll
                for (int kc = 0; kc < 4; kc += 2) {
                    unsigned k0, k1, k2, k3;
                    ldsm_x2(smem_u32(&kf[(nt * 8 + krow) * 72 + kc * 16 + ksel]), k0, k1);
                    ldsm_x2(smem_u32(&kf[(nt * 8 + krow) * 72 + (kc + 1) * 16 + ksel]), k2, k3);
                    mma_fp16(aA0, aA1, aA2, aA3, quf[kc][0], quf[kc][1], quf[kc][2], quf[kc][3], k0, k1);
                    mma_fp16(aB0, aB1, aB2, aB3, quf[kc + 1][0], quf[kc + 1][1], quf[kc + 1][2], quf[kc + 1][3], k2, k3);
                }
                int col = nt * 8 + 2 * tig;
                sf[nt][0] = aA0 + aB0 + GSw[gid * 88 + col - gid + 15] + MSK[col];
                sf[nt][1] = aA1 + aB1 + GSw[gid * 88 + col - gid + 16] + MSK[col + 1];
                sf[nt][2] = aA2 + aB2 + GSw[(gid + 8) * 88 + col - gid + 7] + MSK[col];
                sf[nt][3] = aA3 + aB3 + GSw[(gid + 8) * 88 + col - gid + 8] + MSK[col + 1];
            }
        }

        // ---- online softmax ----
        float mx0 = -1e30f, mx1 = -1e30f;
#pragma unroll
        for (int nt = 0; nt < 8; nt++) {
            mx0 = fmaxf(mx0, fmaxf(sf[nt][0], sf[nt][1]));
            mx1 = fmaxf(mx1, fmaxf(sf[nt][2], sf[nt][3]));
        }
        mx0 = fmaxf(mx0, __shfl_xor_sync(0xffffffffu, mx0, 1));
        mx0 = fmaxf(mx0, __shfl_xor_sync(0xffffffffu, mx0, 2));
        mx1 = fmaxf(mx1, __shfl_xor_sync(0xffffffffu, mx1, 1));
        mx1 = fmaxf(mx1, __shfl_xor_sync(0xffffffffu, mx1, 2));
        float mn0 = fmaxf(mr0, mx0), mn1 = fmaxf(mr1, mx1);
        float sc0 = __expf(mr0 - mn0), sc1 = __expf(mr1 - mn1);
        float su0 = 0.f, su1 = 0.f;
#pragma unroll
        for (int nt = 0; nt < 8; nt++) {
            sf[nt][0] = __expf(sf[nt][0] - mn0);
            sf[nt][1] = __expf(sf[nt][1] - mn0);
            sf[nt][2] = __expf(sf[nt][2] - mn1);
            sf[nt][3] = __expf(sf[nt][3] - mn1);
            su0 += sf[nt][0] + sf[nt][1];
            su1 += sf[nt][2] + sf[nt][3];
        }
        su0 += __shfl_xor_sync(0xffffffffu, su0, 1);
        su0 += __shfl_xor_sync(0xffffffffu, su0, 2);
        su1 += __shfl_xor_sync(0xffffffffu, su1, 1);
        su1 += __shfl_xor_sync(0xffffffffu, su1, 2);
        l0 = l0 * sc0 + su0;
        l1 = l1 * sc1 + su1;
        mr0 = mn0; mr1 = mn1;
#pragma unroll
        for (int nt = 0; nt < 8; nt++) {
            o[nt][0] *= sc0;  o[nt][1] *= sc0;
            o[nt][2] *= sc1;  o[nt][3] *= sc1;
            oL[nt][0] *= sc0; oL[nt][1] *= sc0;
            oL[nt][2] *= sc1; oL[nt][3] *= sc1;
        }

        // ---- O += P @ V (bf16x3, split chains) ----
        {
            int vrow = lane & 7;
            int vsel = ((lane >> 3) & 1) << 3;
#pragma unroll
            for (int kc = 0; kc < 4; kc++) {
                unsigned ah[4], al[4];
                pack_hl(sf[2 * kc][0], sf[2 * kc][1], ah[0], al[0]);
                pack_hl(sf[2 * kc][2], sf[2 * kc][3], ah[1], al[1]);
                pack_hl(sf[2 * kc + 1][0], sf[2 * kc + 1][1], ah[2], al[2]);
                pack_hl(sf[2 * kc + 1][2], sf[2 * kc + 1][3], ah[3], al[3]);
#pragma unroll
                for (int nt = 0; nt < 8; nt++) {
                    unsigned v0, v1, w0, w1;
                    ldsm_x2(smem_u32(&vh[(nt * 8 + vrow) * 72 + kc * 16 + vsel]), v0, v1);
                    ldsm_x2(smem_u32(&vl[(nt * 8 + vrow) * 72 + kc * 16 + vsel]), w0, w1);
                    mma_bf16(o[nt][0], o[nt][1], o[nt][2], o[nt][3],
                             ah[0], ah[1], ah[2], ah[3], v0, v1);
                    mma_bf16(oL[nt][0], oL[nt][1], oL[nt][2], oL[nt][3],
                             ah[0], ah[1], ah[2], ah[3], w0, w1);
                    mma_bf16(oL[nt][0], oL[nt][1], oL[nt][2], oL[nt][3],
                             al[0], al[1], al[2], al[3], v0, v1);
                }
            }
        }
        __syncthreads();
    }

    // ---- epilogue ----
    float inv0 = (l0 > 0.f) ? 1.f / l0 : 0.f;
    float inv1 = (l1 > 0.f) ? 1.f / l1 : 0.f;
    int row0 = t0 + warp * 16 + gid;
#pragma unroll
    for (int nt = 0; nt < 8; nt++) {
        int colg = h * DK_ + nt * 8 + 2 * tig;
        float2 w0 = make_float2((o[nt][0] + oL[nt][0]) * inv0, (o[nt][1] + oL[nt][1]) * inv0);
        *(float2*)&g_ctx[((size_t)(b * T_ + row0)) * F_ + colg] = w0;
        float2 w1 = make_float2((o[nt][2] + oL[nt][2]) * inv1, (o[nt][3] + oL[nt][3]) * inv1);
        *(float2*)&g_ctx[((size_t)(b * T_ + row0 + 8)) * F_ + colg] = w1;
    }
}

// =====================================================================
extern "C" void kernel_launch(void* const* d_in, const int* in_sizes, int n_in,
                              void* d_out, int out_size)
{
    const float* query   = (const float*)d_in[0];
    const float* key_in  = (const float*)d_in[1];
    const float* value   = (const float*)d_in[2];
    const float* pos_emb = (const float*)d_in[3];
    const int*   mask    = (const int*)d_in[4];
    const float* Wq = (const float*)d_in[5];
    const float* bq = (const float*)d_in[6];
    const float* Wk = (const float*)d_in[7];
    const float* bk = (const float*)d_in[8];
    const float* Wv = (const float*)d_in[9];
    const float* bv = (const float*)d_in[10];
    const float* Wo = (const float*)d_in[11];
    const float* bo = (const float*)d_in[12];
    const float* Wp = (const float*)d_in[13];
    const float* pu = (const float*)d_in[14];
    const float* pv = (const float*)d_in[15];
    float* out = (float*)d_out;

    float *Qp, *Cp;
    __half *Kfp, *Pfp;
    __nv_bfloat16 *Vthp, *Vtlp;
    cudaGetSymbolAddress((void**)&Qp,   g_Q);
    cudaGetSymbolAddress((void**)&Cp,   g_ctx);
    cudaGetSymbolAddress((void**)&Kfp,  g_Kf);
    cudaGetSymbolAddress((void**)&Vthp, g_Vth);
    cudaGetSymbolAddress((void**)&Vtlp, g_Vtl);
    cudaGetSymbolAddress((void**)&Pfp,  g_Pf);

    cudaFuncSetAttribute(flash_kernel, cudaFuncAttributeMaxDynamicSharedMemorySize, FL_SMEM);

    // ---- all 4 input projections in ONE launch (grid.z = job id) ----
    GemmJobs pj;
    pj.j[0] = { query,   Wq, bq,      Qp,      nullptr,                 nullptr, B_ * T_, 0 };
    pj.j[1] = { key_in,  Wk, bk,      nullptr, (__nv_bfloat16*)Kfp,     nullptr, B_ * T_, 1 };
    pj.j[2] = { value,   Wv, bv,      nullptr, Vthp,                    Vtlp,    B_ * T_, 2 };
    pj.j[3] = { pos_emb, Wp, nullptr, nullptr, (__nv_bfloat16*)Pfp,     nullptr, P_,      1 };
    gemm_multi<<<dim3(4, 64, 4), 256>>>(pj);

    // fused attention (scores fp16 + rel-shift + softmax + AV bf16x3)
    flash_kernel<<<dim3(8, B_ * H_), 256, FL_SMEM>>>(pu, pv, mask);

    // output projection
    GemmJobs oj;
    oj.j[0] = { Cp, Wo, bo, out, nullptr, nullptr, B_ * T_, 0 };
    oj.j[1] = oj.j[0]; oj.j[2] = oj.j[0]; oj.j[3] = oj.j[0];
    gemm_multi<<<dim3(4, 64, 1), 256>>>(oj);
}